// round 4
// baseline (speedup 1.0000x reference)
#include <cuda_runtime.h>
#include <math.h>

#define KTOP 50
#define TT   40
#define VV   30000
#define THH  800
#define EHH  200
#define EE   300
#define EP   304            // padded E (multiple of 8)
#define LL   3
#define BB   100

#define EPSF   1e-6f
#define DELTAF 0.005f
#define LOGDF  -5.2983173665480363f

#define TCH 8
#define MCH (TCH*KTOP)      // 400 rows per logits chunk
#define NCHUNK (TT/TCH)     // 5

// ------------- static device scratch -------------
__device__ float  d_x[TT*EHH];
__device__ float  d_y[TT*EHH];
__device__ float  d_gin[TT*4*EHH];
__device__ float  d_whh4[LL*4*EHH*EHH];
__device__ float  d_eta[TT*KTOP];
__device__ float  d_alphas[TT*KTOP*EP];
__device__ float  d_wembp[VV*EP];
__device__ float  d_hth[BB*THH];
__device__ float  d_mu_t[BB*KTOP];
__device__ float  d_ls_t[BB*KTOP];
__device__ float  d_theta[BB*KTOP];
__device__ float  d_rowmax[MCH];
__device__ float  d_rowinv[MCH];
__device__ double d_scald[4];   // 0:sum(log*bows) 1:kl_alpha 2:kl_eta 3:kl_theta
__device__ float  d_logits[(size_t)MCH*VV];

// ------------- helpers -------------
__device__ __forceinline__ float warp_sum(float v) {
#pragma unroll
    for (int o = 16; o; o >>= 1) v += __shfl_xor_sync(0xffffffffu, v, o);
    return v;
}
__device__ __forceinline__ float sigmf(float x) { return 1.f / (1.f + __expf(-x)); }

__device__ __forceinline__ void block_add_double(float v, int slot) {
    __shared__ float red[8];
    int lane = threadIdx.x & 31, wid = threadIdx.x >> 5;
    v = warp_sum(v);
    if (lane == 0) red[wid] = v;
    __syncthreads();
    if (threadIdx.x == 0) {
        float tot = 0.f;
        int nw = (blockDim.x + 31) >> 5;
        for (int w = 0; w < nw; w++) tot += red[w];
        atomicAdd(&d_scald[slot], (double)tot);
    }
}

// ------------- zero -------------
__global__ void k_zero() {
    int i = blockIdx.x * blockDim.x + threadIdx.x;
    if (i < BB*THH) d_hth[i] = 0.f;
    if (i < TT*EHH) d_x[i] = 0.f;
    if (i < 4) d_scald[i] = 0.0;
}

// ------------- pack Whh: [l][j4][r][jj] -------------
__global__ void k_pack_whh(const float* __restrict__ Whh) {
    int idx = blockIdx.x * blockDim.x + threadIdx.x;
    if (idx >= LL*4*EHH*EHH) return;
    int l = idx / (4*EHH*EHH);
    int rem = idx % (4*EHH*EHH);
    int j4 = rem / (4*EHH*4);
    int rem2 = rem % (4*EHH*4);
    int r = rem2 >> 2, jj = rem2 & 3;
    d_whh4[idx] = Whh[l*4*EHH*EHH + r*EHH + j4*4 + jj];
}

// ------------- alphas transpose+pad, word_emb pad -------------
__global__ void k_alphaT(const float* __restrict__ mq) {
    int idx = blockIdx.x * blockDim.x + threadIdx.x;
    if (idx >= TT*KTOP*EP) return;
    int row = idx / EP, e = idx % EP;
    int t = row / KTOP, k = row % KTOP;
    d_alphas[idx] = (e < EE) ? mq[(k*TT + t)*EE + e] : 0.f;
}
__global__ void k_wembpad(const float* __restrict__ we) {
    int idx = blockIdx.x * blockDim.x + threadIdx.x;
    if (idx >= VV*EP) return;
    int v = idx / EP, e = idx % EP;
    d_wembp[idx] = (e < EE) ? we[v*EE + e] : 0.f;
}

// ------------- generic split-K SGEMM, atomic accumulate -------------
// C[m,n] += sum_k A[m,k]*B[n,k] over this block's K chunk
__global__ void __launch_bounds__(256) k_sgemm_atomic(
        const float* __restrict__ A, int lda,
        const float* __restrict__ B, int ldb,
        float* __restrict__ C, int M, int N, int kchunk) {
    __shared__ float As[8][64];
    __shared__ float Bs[8][64];
    const int k0b = blockIdx.z * kchunk;
    const int bm = blockIdx.y * 64, bn = blockIdx.x * 64;
    const int tid = threadIdx.x;
    const int lr = tid >> 2, lk = (tid & 3) * 2;
    const int tx = tid & 15, ty = tid >> 4;
    float acc[4][4];
#pragma unroll
    for (int i = 0; i < 4; i++)
#pragma unroll
        for (int j = 0; j < 4; j++) acc[i][j] = 0.f;

    const int kend = k0b + kchunk;
    for (int k0 = k0b; k0 < kend; k0 += 8) {
        float2 av = make_float2(0.f,0.f), bv = make_float2(0.f,0.f);
        int am = bm + lr, bn2 = bn + lr;
        if (am < M) av = *(const float2*)&A[(size_t)am*lda + k0 + lk];
        if (bn2 < N) bv = *(const float2*)&B[(size_t)bn2*ldb + k0 + lk];
        As[lk][lr] = av.x; As[lk+1][lr] = av.y;
        Bs[lk][lr] = bv.x; Bs[lk+1][lr] = bv.y;
        __syncthreads();
#pragma unroll
        for (int kk = 0; kk < 8; kk++) {
            float a[4], b[4];
            *(float4*)a = *(const float4*)&As[kk][ty*4];
            *(float4*)b = *(const float4*)&Bs[kk][tx*4];
#pragma unroll
            for (int i = 0; i < 4; i++)
#pragma unroll
                for (int j = 0; j < 4; j++) acc[i][j] += a[i]*b[j];
        }
        __syncthreads();
    }
#pragma unroll
    for (int i = 0; i < 4; i++) {
        int m = bm + ty*4 + i;
        if (m >= M) continue;
#pragma unroll
        for (int j = 0; j < 4; j++) {
            int n = bn + tx*4 + j;
            if (n < N) atomicAdd(&C[(size_t)m*N + n], acc[i][j]);
        }
    }
}

__global__ void k_addbias(const float* __restrict__ b_map) {
    int i = blockIdx.x * blockDim.x + threadIdx.x;
    if (i < TT*EHH) d_x[i] += b_map[i % EHH];
}

// ------------- LSTM input gates (parallel over t) -------------
__global__ void k_gin(const float* __restrict__ Wih, const float* __restrict__ bih,
                      const float* __restrict__ bhh, const float* __restrict__ x, int l) {
    int w = (blockIdx.x * blockDim.x + threadIdx.x) >> 5;
    int lane = threadIdx.x & 31;
    if (w >= TT*4*EHH) return;
    int t = w / (4*EHH), r = w % (4*EHH);
    const float* wr = Wih + (size_t)l*4*EHH*EHH + (size_t)r*EHH;
    const float* xr = x + t*EHH;
    float s = 0.f;
    for (int j = lane; j < EHH; j += 32) s += wr[j]*xr[j];
    s = warp_sum(s);
    if (lane == 0) d_gin[t*4*EHH + r] = s + bih[l*4*EHH + r] + bhh[l*4*EHH + r];
}

// ------------- LSTM recurrence: single block, 800 threads -------------
__global__ void k_lstm_rec(float* __restrict__ out, int l) {
    __shared__ float h_sh[EHH];
    __shared__ float g_sh[4*EHH];
    int r = threadIdx.x;
    if (r < EHH) h_sh[r] = 0.f;
    float c = 0.f;
    __syncthreads();
    const float4* W = (const float4*)d_whh4 + (size_t)l * (EHH/4) * (4*EHH);
    for (int t = 0; t < TT; t++) {
        float acc = d_gin[t*4*EHH + r];
#pragma unroll 10
        for (int j4 = 0; j4 < EHH/4; j4++) {
            float4 w = W[j4*(4*EHH) + r];
            acc += w.x*h_sh[j4*4] + w.y*h_sh[j4*4+1] + w.z*h_sh[j4*4+2] + w.w*h_sh[j4*4+3];
        }
        g_sh[r] = acc;
        __syncthreads();
        if (r < EHH) {
            float ig = sigmf(g_sh[r]);
            float fg = sigmf(g_sh[EHH + r]);
            float gg = tanhf(g_sh[2*EHH + r]);
            float og = sigmf(g_sh[3*EHH + r]);
            c = fg*c + ig*gg;
            float h = og*tanhf(c);
            h_sh[r] = h;
            out[t*EHH + r] = h;
        }
        __syncthreads();
    }
}

// ------------- eta chain (sequential over T, 1 block) -------------
__global__ void k_eta(const float* __restrict__ Wmu, const float* __restrict__ bmu,
                      const float* __restrict__ Wls, const float* __restrict__ bls) {
    __shared__ float inp[EHH+KTOP];
    __shared__ float mu_s[KTOP], ls_s[KTOP], eta_s[KTOP];
    int tid = threadIdx.x, lane = tid & 31, wid = tid >> 5;
    float kl_acc = 0.f;
    for (int t = 0; t < TT; t++) {
        if (tid < EHH) inp[tid] = d_y[t*EHH + tid];
        else if (tid < EHH+KTOP) inp[tid] = (t == 0) ? 0.f : eta_s[tid - EHH];
        __syncthreads();
        for (int o = wid; o < 2*KTOP; o += 8) {
            const float* W = (o < KTOP) ? (Wmu + o*(EHH+KTOP)) : (Wls + (o-KTOP)*(EHH+KTOP));
            float s = 0.f;
            for (int j = lane; j < EHH+KTOP; j += 32) s += W[j]*inp[j];
            s = warp_sum(s);
            if (lane == 0) {
                if (o < KTOP) mu_s[o] = s + bmu[o];
                else          ls_s[o-KTOP] = s + bls[o-KTOP];
            }
        }
        __syncthreads();
        if (tid < KTOP) {
            float mu = mu_s[tid], ls = ls_s[tid];
            float term;
            if (t == 0) term = 0.5f*((__expf(ls) + mu*mu)/(1.f+EPSF) - 1.f - ls);
            else {
                float dd = mu - eta_s[tid];
                term = 0.5f*((__expf(ls) + dd*dd)/(DELTAF+EPSF) - 1.f + LOGDF - ls);
            }
            kl_acc += term;
            d_eta[t*KTOP + tid] = mu;
        }
        __syncthreads();
        if (tid < KTOP) eta_s[tid] = mu_s[tid];
        __syncthreads();
    }
    block_add_double(kl_acc, 2);
}

// ------------- theta hidden epilogue -------------
__global__ void k_theta_h(const float* __restrict__ b_theta, const float* __restrict__ W_theta,
                          const int* __restrict__ times) {
    int idx = blockIdx.x * blockDim.x + threadIdx.x;
    if (idx >= BB*THH) return;
    int b = idx / THH, i = idx % THH;
    int tb = times[b];
    float v = d_hth[idx] + b_theta[i];
    const float* wrow = W_theta + (size_t)i*(VV+KTOP) + VV;
    const float* er = d_eta + tb*KTOP;
#pragma unroll 10
    for (int k = 0; k < KTOP; k++) v += er[k]*wrow[k];
    d_hth[idx] = tanhf(v);
}

// ------------- mu_t / ls_t -------------
__global__ void k_theta_muls(const float* __restrict__ Wmu, const float* __restrict__ bmu,
                             const float* __restrict__ Wls, const float* __restrict__ bls) {
    int w = (blockIdx.x * blockDim.x + threadIdx.x) >> 5;
    int lane = threadIdx.x & 31;
    if (w >= BB*2*KTOP) return;
    int b = w / (2*KTOP), q = w % (2*KTOP);
    int kk = q % KTOP;
    bool isls = q >= KTOP;
    const float* W = (isls ? Wls : Wmu) + kk*THH;
    const float* h = d_hth + b*THH;
    float s = 0.f;
    for (int j = lane; j < THH; j += 32) s += W[j]*h[j];
    s = warp_sum(s);
    if (lane == 0) {
        s += (isls ? bls : bmu)[kk];
        (isls ? d_ls_t : d_mu_t)[b*KTOP + kk] = s;
    }
}

// ------------- theta softmax + kl_theta -------------
__global__ void k_theta_softkl(const int* __restrict__ times) {
    __shared__ float mus[KTOP], es[KTOP], red2[2];
    int b = blockIdx.x, tid = threadIdx.x;
    if (tid < KTOP) mus[tid] = d_mu_t[b*KTOP + tid];
    __syncthreads();
    if (tid == 0) {
        float m = -1e30f;
        for (int k = 0; k < KTOP; k++) m = fmaxf(m, mus[k]);
        red2[0] = m;
    }
    __syncthreads();
    if (tid < KTOP) es[tid] = __expf(mus[tid] - red2[0]);
    __syncthreads();
    if (tid == 0) {
        float s = 0.f;
        for (int k = 0; k < KTOP; k++) s += es[k];
        red2[1] = 1.f/s;
    }
    __syncthreads();
    float kl = 0.f;
    if (tid < KTOP) {
        d_theta[b*KTOP + tid] = es[tid]*red2[1];
        float ls = d_ls_t[b*KTOP + tid];
        float e  = d_eta[times[b]*KTOP + tid];
        float dmu = mus[tid] - e;
        kl = 0.5f*((__expf(ls) + dmu*dmu)/(1.f+EPSF) - 1.f - ls);
    }
    block_add_double(kl, 3);
}

// ------------- kl_alpha -------------
__global__ void k_klalpha(const float* __restrict__ mq, const float* __restrict__ lsq) {
    int idx = blockIdx.x * blockDim.x + threadIdx.x;
    float term = 0.f;
    if (idx < KTOP*TT*EE) {
        int t = (idx / EE) % TT;
        float mu = mq[idx], ls = lsq[idx];
        if (t == 0) term = 0.5f*((__expf(ls) + mu*mu)/(1.f+EPSF) - 1.f - ls);
        else {
            float d = mu - mq[idx - EE];
            term = 0.5f*((__expf(ls) + d*d)/(DELTAF+EPSF) - 1.f + LOGDF - ls);
        }
    }
    block_add_double(term, 1);
}

// ------------- logits GEMM chunk (direct store) -------------
__global__ void __launch_bounds__(256) k_gemm_logits(int ch) {
    __shared__ float As[8][64];
    __shared__ float Bs[8][64];
    const int bm = blockIdx.y * 64, bn = blockIdx.x * 64;
    const int tid = threadIdx.x;
    const int lr = tid >> 2, lk = (tid & 3) * 2;
    const int tx = tid & 15, ty = tid >> 4;
    float acc[4][4];
#pragma unroll
    for (int i = 0; i < 4; i++)
#pragma unroll
        for (int j = 0; j < 4; j++) acc[i][j] = 0.f;

    const float* A = d_alphas + (size_t)ch*MCH*EP;
    for (int k0 = 0; k0 < EP; k0 += 8) {
        float2 av = make_float2(0.f,0.f), bv = make_float2(0.f,0.f);
        int am = bm + lr, bn2 = bn + lr;
        if (am < MCH) av = *(const float2*)&A[(size_t)am*EP + k0 + lk];
        if (bn2 < VV) bv = *(const float2*)&d_wembp[(size_t)bn2*EP + k0 + lk];
        As[lk][lr] = av.x; As[lk+1][lr] = av.y;
        Bs[lk][lr] = bv.x; Bs[lk+1][lr] = bv.y;
        __syncthreads();
#pragma unroll
        for (int kk = 0; kk < 8; kk++) {
            float a[4], b[4];
            *(float4*)a = *(const float4*)&As[kk][ty*4];
            *(float4*)b = *(const float4*)&Bs[kk][tx*4];
#pragma unroll
            for (int i = 0; i < 4; i++)
#pragma unroll
                for (int j = 0; j < 4; j++) acc[i][j] += a[i]*b[j];
        }
        __syncthreads();
    }
#pragma unroll
    for (int i = 0; i < 4; i++) {
        int m = bm + ty*4 + i;
        if (m >= MCH) continue;
#pragma unroll
        for (int j = 0; j < 4; j++) {
            int n = bn + tx*4 + j;
            if (n < VV) d_logits[(size_t)m*VV + n] = acc[i][j];
        }
    }
}

// ------------- per-row softmax stats -------------
__global__ void k_rowstats() {
    __shared__ float red[8];
    int row = blockIdx.x;
    const float* p = d_logits + (size_t)row*VV;
    int tid = threadIdx.x, lane = tid & 31, wid = tid >> 5;
    float m = -1e30f;
    for (int v = tid; v < VV; v += 256) m = fmaxf(m, p[v]);
#pragma unroll
    for (int o = 16; o; o >>= 1) m = fmaxf(m, __shfl_xor_sync(0xffffffffu, m, o));
    if (lane == 0) red[wid] = m;
    __syncthreads();
    if (tid == 0) {
        float mm = red[0];
        for (int w = 1; w < 8; w++) mm = fmaxf(mm, red[w]);
        red[0] = mm;
    }
    __syncthreads();
    float mx = red[0];
    float s = 0.f;
    for (int v = tid; v < VV; v += 256) s += __expf(p[v] - mx);
    s = warp_sum(s);
    __syncthreads();
    if (lane == 0) red[wid] = s;
    __syncthreads();
    if (tid == 0) {
        float tot = 0.f;
        for (int w = 0; w < 8; w++) tot += red[w];
        d_rowmax[row] = mx;
        d_rowinv[row] = 1.f/tot;
    }
}

// ------------- nll partial over this chunk -------------
__global__ void k_nll(const float* __restrict__ bows, const int* __restrict__ times, int ch) {
    __shared__ float wsh[KTOP], msh[KTOP];
    int b = blockIdx.y;
    int t = times[b];
    if (t / TCH != ch) return;
    int tloc = t % TCH;
    int tid = threadIdx.x;
    if (tid < KTOP) {
        int row = tloc*KTOP + tid;
        wsh[tid] = d_theta[b*KTOP + tid] * d_rowinv[row];
        msh[tid] = d_rowmax[row];
    }
    __syncthreads();
    int v = blockIdx.x * blockDim.x + tid;
    float val = 0.f;
    if (v < VV) {
        const float* base = d_logits + (size_t)tloc*KTOP*VV + v;
        float p = 0.f;
#pragma unroll 10
        for (int k = 0; k < KTOP; k++)
            p += wsh[k] * __expf(base[(size_t)k*VV] - msh[k]);
        val = __logf(p + EPSF) * bows[(size_t)b*VV + v];
    }
    block_add_double(val, 0);
}

// ------------- finalize -------------
__global__ void k_finalize(float* out, int n) {
    if (threadIdx.x == 0) {
        float nll = -(float)d_scald[0];
        float ka = (float)d_scald[1];
        float ke = (float)d_scald[2];
        float kt = (float)d_scald[3];
        float vals[5] = {nll + ka + ke + kt, nll, ka, ke, kt};
        for (int i = 0; i < n; i++) out[i] = (i < 5) ? vals[i] : 0.f;
    }
}

extern "C" void kernel_launch(void* const* d_in, const int* in_sizes, int n_in,
                              void* d_out, int out_size) {
    const float* bows      = (const float*)d_in[0];
    const float* nbows     = (const float*)d_in[1];
    const float* rnn_inp   = (const float*)d_in[2];
    const float* word_emb  = (const float*)d_in[3];
    const float* mu_q_a    = (const float*)d_in[4];
    const float* ls_q_a    = (const float*)d_in[5];
    const float* W_theta   = (const float*)d_in[6];
    const float* b_theta   = (const float*)d_in[7];
    const float* W_mu_th   = (const float*)d_in[8];
    const float* b_mu_th   = (const float*)d_in[9];
    const float* W_ls_th   = (const float*)d_in[10];
    const float* b_ls_th   = (const float*)d_in[11];
    const float* W_map     = (const float*)d_in[12];
    const float* b_map     = (const float*)d_in[13];
    const float* lstm_Wih  = (const float*)d_in[14];
    const float* lstm_Whh  = (const float*)d_in[15];
    const float* lstm_bih  = (const float*)d_in[16];
    const float* lstm_bhh  = (const float*)d_in[17];
    const float* W_mu_eta  = (const float*)d_in[18];
    const float* b_mu_eta  = (const float*)d_in[19];
    const float* W_ls_eta  = (const float*)d_in[20];
    const float* b_ls_eta  = (const float*)d_in[21];
    const int*   times     = (const int*)d_in[22];
    float* out = (float*)d_out;

    float *dx, *dy, *dwhh, *dhth, *dlog;
    cudaGetSymbolAddress((void**)&dx, d_x);
    cudaGetSymbolAddress((void**)&dy, d_y);
    cudaGetSymbolAddress((void**)&dwhh, d_whh4);
    cudaGetSymbolAddress((void**)&dhth, d_hth);
    cudaGetSymbolAddress((void**)&dlog, d_logits);

    k_zero<<<(BB*THH + 255)/256, 256>>>();
    k_pack_whh<<<(LL*4*EHH*EHH + 255)/256, 256>>>(lstm_Whh);
    k_alphaT<<<(TT*KTOP*EP + 255)/256, 256>>>(mu_q_a);
    k_wembpad<<<(VV*EP + 255)/256, 256>>>(word_emb);

    // x = rnn_inp @ W_map^T : M=40, N=200, K=30000, split-K z=25
    {
        dim3 g((EHH + 63)/64, (TT + 63)/64, 25);
        k_sgemm_atomic<<<g, 256>>>(rnn_inp, VV, W_map, VV, dx, TT, EHH, 1200);
    }
    k_addbias<<<(TT*EHH + 255)/256, 256>>>(b_map);

    // LSTM layers (ping-pong x/y)
    float* lin = dx; float* lout = dy;
    for (int l = 0; l < LL; l++) {
        k_gin<<<(TT*4*EHH*32 + 255)/256, 256>>>(lstm_Wih, lstm_bih, lstm_bhh, lin, l);
        k_lstm_rec<<<1, 800>>>(lout, l);
        float* tmp = lin; lin = lout; lout = tmp;
    }
    // after 3 layers final output is in d_y (lin points at it after swap)
    if (lin != dy) {
        cudaMemcpyAsync(dy, lin, TT*EHH*sizeof(float), cudaMemcpyDeviceToDevice);
    }

    k_eta<<<1, 256>>>(W_mu_eta, b_mu_eta, W_ls_eta, b_ls_eta);

    // hth = nbows @ W_theta[:, :V]^T : M=100, N=800, K=30000, split-K z=15
    {
        dim3 g((THH + 63)/64, (BB + 63)/64, 15);
        k_sgemm_atomic<<<g, 256>>>(nbows, VV, W_theta, VV + KTOP, dhth, BB, THH, 2000);
    }
    k_theta_h<<<(BB*THH + 255)/256, 256>>>(b_theta, W_theta, times);
    k_theta_muls<<<(BB*2*KTOP*32 + 255)/256, 256>>>(W_mu_th, b_mu_th, W_ls_th, b_ls_th);
    k_theta_softkl<<<BB, 64>>>(times);

    k_klalpha<<<(KTOP*TT*EE + 255)/256, 256>>>(mu_q_a, ls_q_a);

    // logits chunks
    for (int ch = 0; ch < NCHUNK; ch++) {
        dim3 g((VV + 63)/64, (MCH + 63)/64);
        k_gemm_logits<<<g, 256>>>(ch);
        k_rowstats<<<MCH, 256>>>();
        dim3 gn((VV + 255)/256, BB);
        k_nll<<<gn, 256>>>(bows, times, ch);
    }

    k_finalize<<<1, 32>>>(out, out_size);
}

// round 6
// speedup vs baseline: 1.2166x; 1.2166x over previous
#include <cuda_runtime.h>
#include <math.h>

#define KTOP 50
#define TT   40
#define VV   30000
#define VP   30080          // 235*128
#define THH  800
#define EHH  200
#define EE   300
#define EP   304            // padded E (multiple of 8)
#define LL   3
#define BB   100
#define MP   2048           // padded logits rows (16*128), real rows = 2000

#define EPSF   1e-6f
#define DELTAF 0.005f
#define LOGDF  -5.2983173665480363f

// ------------- static device scratch -------------
__device__ float  d_x[TT*EHH];
__device__ float  d_y[TT*EHH];
__device__ float  d_gin[TT*4*EHH];
__device__ float  d_whh4[LL*4*EHH*EHH];
__device__ float  d_eta[TT*KTOP];
__device__ float  d_alphas[MP*EP];
__device__ float  d_wembp[(size_t)VP*EP];
__device__ float  d_hth[BB*THH];
__device__ float  d_mu_t[BB*KTOP];
__device__ float  d_ls_t[BB*KTOP];
__device__ float  d_theta[BB*KTOP];
__device__ float  d_rowsum[MP];
__device__ double d_scald[4];   // 0:sum(log*bows) 1:kl_alpha 2:kl_eta 3:kl_theta
__device__ float  d_elog[(size_t)MP*VP];   // exp(logits), ~246 MB

// ------------- helpers -------------
__device__ __forceinline__ float warp_sum(float v) {
#pragma unroll
    for (int o = 16; o; o >>= 1) v += __shfl_xor_sync(0xffffffffu, v, o);
    return v;
}
__device__ __forceinline__ float sigmf(float x) { return 1.f / (1.f + __expf(-x)); }

__device__ __forceinline__ void block_add_double(float v, int slot) {
    __shared__ float red[8];
    int lane = threadIdx.x & 31, wid = threadIdx.x >> 5;
    v = warp_sum(v);
    if (lane == 0) red[wid] = v;
    __syncthreads();
    if (threadIdx.x == 0) {
        float tot = 0.f;
        int nw = (blockDim.x + 31) >> 5;
        for (int w = 0; w < nw; w++) tot += red[w];
        atomicAdd(&d_scald[slot], (double)tot);
    }
}

// ------------- zero -------------
__global__ void k_zero() {
    int i = blockIdx.x * blockDim.x + threadIdx.x;
    if (i < BB*THH) d_hth[i] = 0.f;
    if (i < TT*EHH) d_x[i] = 0.f;
    if (i < MP)     d_rowsum[i] = 0.f;
    if (i < 4)      d_scald[i] = 0.0;
}

// ------------- pack Whh: [l][j4][r][jj] -------------
__global__ void k_pack_whh(const float* __restrict__ Whh) {
    int idx = blockIdx.x * blockDim.x + threadIdx.x;
    if (idx >= LL*4*EHH*EHH) return;
    int l = idx / (4*EHH*EHH);
    int rem = idx % (4*EHH*EHH);
    int j4 = rem / (4*EHH*4);
    int rem2 = rem % (4*EHH*4);
    int r = rem2 >> 2, jj = rem2 & 3;
    d_whh4[idx] = Whh[l*4*EHH*EHH + r*EHH + j4*4 + jj];
}

// ------------- alphas transpose+pad [MP][EP], word_emb pad [VP][EP] -------------
__global__ void k_alphaT(const float* __restrict__ mq) {
    int idx = blockIdx.x * blockDim.x + threadIdx.x;
    if (idx >= MP*EP) return;
    int row = idx / EP, e = idx % EP;
    int t = row / KTOP, k = row % KTOP;
    d_alphas[idx] = (row < TT*KTOP && e < EE) ? mq[(k*TT + t)*EE + e] : 0.f;
}
__global__ void k_wembpad(const float* __restrict__ we) {
    size_t idx = (size_t)blockIdx.x * blockDim.x + threadIdx.x;
    if (idx >= (size_t)VP*EP) return;
    int v = (int)(idx / EP), e = (int)(idx % EP);
    d_wembp[idx] = (v < VV && e < EE) ? we[(size_t)v*EE + e] : 0.f;
}

// ------------- generic split-K SGEMM (W_map path) -------------
__global__ void __launch_bounds__(256) k_sgemm_atomic(
        const float* __restrict__ A, int lda,
        const float* __restrict__ B, int ldb,
        float* __restrict__ C, int M, int N, int kchunk) {
    __shared__ float As[8][64];
    __shared__ float Bs[8][64];
    const int k0b = blockIdx.z * kchunk;
    const int bm = blockIdx.y * 64, bn = blockIdx.x * 64;
    const int tid = threadIdx.x;
    const int lr = tid >> 2, lk = (tid & 3) * 2;
    const int tx = tid & 15, ty = tid >> 4;
    float acc[4][4];
#pragma unroll
    for (int i = 0; i < 4; i++)
#pragma unroll
        for (int j = 0; j < 4; j++) acc[i][j] = 0.f;

    const int kend = k0b + kchunk;
    for (int k0 = k0b; k0 < kend; k0 += 8) {
        float2 av = make_float2(0.f,0.f), bv = make_float2(0.f,0.f);
        int am = bm + lr, bn2 = bn + lr;
        if (am < M) av = *(const float2*)&A[(size_t)am*lda + k0 + lk];
        if (bn2 < N) bv = *(const float2*)&B[(size_t)bn2*ldb + k0 + lk];
        As[lk][lr] = av.x; As[lk+1][lr] = av.y;
        Bs[lk][lr] = bv.x; Bs[lk+1][lr] = bv.y;
        __syncthreads();
#pragma unroll
        for (int kk = 0; kk < 8; kk++) {
            float a[4], b[4];
            *(float4*)a = *(const float4*)&As[kk][ty*4];
            *(float4*)b = *(const float4*)&Bs[kk][tx*4];
#pragma unroll
            for (int i = 0; i < 4; i++)
#pragma unroll
                for (int j = 0; j < 4; j++) acc[i][j] += a[i]*b[j];
        }
        __syncthreads();
    }
#pragma unroll
    for (int i = 0; i < 4; i++) {
        int m = bm + ty*4 + i;
        if (m >= M) continue;
#pragma unroll
        for (int j = 0; j < 4; j++) {
            int n = bn + tx*4 + j;
            if (n < N) atomicAdd(&C[(size_t)m*N + n], acc[i][j]);
        }
    }
}

// ------------- f32x2 SGEMM, 128x128 tile, 8x8 microtile -------------
// MODE 0: split-K via blockIdx.z (K slice = [z*kchunk, (z+1)*kchunk)), atomic
//         accumulate into C, guards on M/N, B loaded via float2 pairs.
// MODE 1: logits path: full K (= kchunk), store exp(acc) to C (padded, no
//         guards), atomicAdd per-row sums of exp.
template<int MODE>
__global__ void __launch_bounds__(256, 1) k_gemm_f32x2(
        const float* __restrict__ A, int lda, int M,
        const float* __restrict__ B, int ldb, int N,
        float* __restrict__ C, int ldc,
        int kchunk, float* __restrict__ rowsum) {
    __shared__ float As[2][8][128];
    __shared__ float Bs[2][8][128];
    const int tid = threadIdx.x;
    const int bm = blockIdx.y * 128, bn = blockIdx.x * 128;
    const int ar  = tid >> 1;          // 0..127
    const int akq = (tid & 1) * 4;     // 0 or 4
    const int tx = tid & 15, ty = tid >> 4;

    const int kk0   = (MODE == 0) ? (int)blockIdx.z * kchunk : 0;
    const int kkend = kk0 + kchunk;

    unsigned long long acc[8][4];
#pragma unroll
    for (int i = 0; i < 8; i++)
#pragma unroll
        for (int j = 0; j < 4; j++) acc[i][j] = 0ull;

    auto ldA = [&](int k) -> float4 {
        if (MODE == 0 && bm + ar >= M) return make_float4(0.f,0.f,0.f,0.f);
        return *(const float4*)&A[(size_t)(bm + ar)*lda + k + akq];
    };
    auto ldB = [&](int k) -> float4 {
        if (MODE == 0) {
            if (bn + ar >= N) return make_float4(0.f,0.f,0.f,0.f);
            const float* p = &B[(size_t)(bn + ar)*ldb + k + akq];
            float2 u = *(const float2*)p;
            float2 v = *(const float2*)(p + 2);
            return make_float4(u.x, u.y, v.x, v.y);
        }
        return *(const float4*)&B[(size_t)(bn + ar)*ldb + k + akq];
    };

    float4 ra = ldA(kk0), rb = ldB(kk0);
    As[0][akq+0][ar] = ra.x; As[0][akq+1][ar] = ra.y;
    As[0][akq+2][ar] = ra.z; As[0][akq+3][ar] = ra.w;
    Bs[0][akq+0][ar] = rb.x; Bs[0][akq+1][ar] = rb.y;
    Bs[0][akq+2][ar] = rb.z; Bs[0][akq+3][ar] = rb.w;
    __syncthreads();

    const int nit = (kkend - kk0) >> 3;
    for (int it = 0; it < nit; it++) {
        int buf = it & 1;
        if (it + 1 < nit) {
            ra = ldA(kk0 + (it+1)*8);
            rb = ldB(kk0 + (it+1)*8);
        }
#pragma unroll
        for (int kk = 0; kk < 8; kk++) {
            float a[8];
            *(float4*)&a[0] = *(const float4*)&As[buf][kk][ty*8];
            *(float4*)&a[4] = *(const float4*)&As[buf][kk][ty*8 + 4];
            unsigned long long b2[4];
            const unsigned long long* bp = (const unsigned long long*)&Bs[buf][kk][tx*8];
            b2[0] = bp[0]; b2[1] = bp[1]; b2[2] = bp[2]; b2[3] = bp[3];
            unsigned long long a2[8];
#pragma unroll
            for (int i = 0; i < 8; i++)
                asm("mov.b64 %0, {%1, %1};" : "=l"(a2[i]) : "f"(a[i]));
#pragma unroll
            for (int i = 0; i < 8; i++)
#pragma unroll
                for (int j = 0; j < 4; j++)
                    asm("fma.rn.f32x2 %0, %1, %2, %0;"
                        : "+l"(acc[i][j]) : "l"(a2[i]), "l"(b2[j]));
        }
        if (it + 1 < nit) {
            int nb = buf ^ 1;
            As[nb][akq+0][ar] = ra.x; As[nb][akq+1][ar] = ra.y;
            As[nb][akq+2][ar] = ra.z; As[nb][akq+3][ar] = ra.w;
            Bs[nb][akq+0][ar] = rb.x; Bs[nb][akq+1][ar] = rb.y;
            Bs[nb][akq+2][ar] = rb.z; Bs[nb][akq+3][ar] = rb.w;
        }
        __syncthreads();
    }

    if (MODE == 0) {
#pragma unroll
        for (int i = 0; i < 8; i++) {
            int m = bm + ty*8 + i;
            if (m >= M) continue;
#pragma unroll
            for (int j = 0; j < 4; j++) {
                float2 v = *(float2*)&acc[i][j];
                int n = bn + tx*8 + 2*j;
                if (n   < N) atomicAdd(&C[(size_t)m*ldc + n],   v.x);
                if (n+1 < N) atomicAdd(&C[(size_t)m*ldc + n+1], v.y);
            }
        }
    } else {
        float rs[8];
        const int nbase = bn + tx*8;
#pragma unroll
        for (int i = 0; i < 8; i++) {
            float e[8];
#pragma unroll
            for (int j = 0; j < 4; j++) {
                float2 v = *(float2*)&acc[i][j];
                e[2*j]   = __expf(v.x);
                e[2*j+1] = __expf(v.y);
            }
#pragma unroll
            for (int jj = 0; jj < 8; jj++)
                if (nbase + jj >= VV) e[jj] = 0.f;
            rs[i] = e[0]+e[1]+e[2]+e[3]+e[4]+e[5]+e[6]+e[7];
            size_t off = (size_t)(bm + ty*8 + i)*ldc + nbase;
            *(float4*)&C[off]     = make_float4(e[0], e[1], e[2], e[3]);
            *(float4*)&C[off + 4] = make_float4(e[4], e[5], e[6], e[7]);
        }
#pragma unroll
        for (int off = 1; off < 16; off <<= 1)
#pragma unroll
            for (int i = 0; i < 8; i++)
                rs[i] += __shfl_xor_sync(0xffffffffu, rs[i], off);
        if ((tid & 15) == 0) {
#pragma unroll
            for (int i = 0; i < 8; i++)
                atomicAdd(&rowsum[bm + ty*8 + i], rs[i]);
        }
    }
}

__global__ void k_addbias(const float* __restrict__ b_map) {
    int i = blockIdx.x * blockDim.x + threadIdx.x;
    if (i < TT*EHH) d_x[i] += b_map[i % EHH];
}

// ------------- LSTM input gates (parallel over t) -------------
__global__ void k_gin(const float* __restrict__ Wih, const float* __restrict__ bih,
                      const float* __restrict__ bhh, const float* __restrict__ x, int l) {
    int w = (blockIdx.x * blockDim.x + threadIdx.x) >> 5;
    int lane = threadIdx.x & 31;
    if (w >= TT*4*EHH) return;
    int t = w / (4*EHH), r = w % (4*EHH);
    const float* wr = Wih + (size_t)l*4*EHH*EHH + (size_t)r*EHH;
    const float* xr = x + t*EHH;
    float s = 0.f;
    for (int j = lane; j < EHH; j += 32) s += wr[j]*xr[j];
    s = warp_sum(s);
    if (lane == 0) d_gin[t*4*EHH + r] = s + bih[l*4*EHH + r] + bhh[l*4*EHH + r];
}

// ------------- LSTM recurrence: single block, 800 threads -------------
__global__ void k_lstm_rec(float* __restrict__ out, int l) {
    __shared__ float h_sh[EHH];
    __shared__ float g_sh[4*EHH];
    int r = threadIdx.x;
    if (r < EHH) h_sh[r] = 0.f;
    float c = 0.f;
    __syncthreads();
    const float4* W = (const float4*)d_whh4 + (size_t)l * (EHH/4) * (4*EHH);
    for (int t = 0; t < TT; t++) {
        float acc = d_gin[t*4*EHH + r];
#pragma unroll 10
        for (int j4 = 0; j4 < EHH/4; j4++) {
            float4 w = W[j4*(4*EHH) + r];
            acc += w.x*h_sh[j4*4] + w.y*h_sh[j4*4+1] + w.z*h_sh[j4*4+2] + w.w*h_sh[j4*4+3];
        }
        g_sh[r] = acc;
        __syncthreads();
        if (r < EHH) {
            float ig = sigmf(g_sh[r]);
            float fg = sigmf(g_sh[EHH + r]);
            float gg = tanhf(g_sh[2*EHH + r]);
            float og = sigmf(g_sh[3*EHH + r]);
            c = fg*c + ig*gg;
            float h = og*tanhf(c);
            h_sh[r] = h;
            out[t*EHH + r] = h;
        }
        __syncthreads();
    }
}

// ------------- eta chain (sequential over T, 1 block) -------------
__global__ void k_eta(const float* __restrict__ Wmu, const float* __restrict__ bmu,
                      const float* __restrict__ Wls, const float* __restrict__ bls) {
    __shared__ float inp[EHH+KTOP];
    __shared__ float mu_s[KTOP], ls_s[KTOP], eta_s[KTOP];
    int tid = threadIdx.x, lane = tid & 31, wid = tid >> 5;
    float kl_acc = 0.f;
    for (int t = 0; t < TT; t++) {
        if (tid < EHH) inp[tid] = d_y[t*EHH + tid];
        else if (tid < EHH+KTOP) inp[tid] = (t == 0) ? 0.f : eta_s[tid - EHH];
        __syncthreads();
        for (int o = wid; o < 2*KTOP; o += 8) {
            const float* W = (o < KTOP) ? (Wmu + o*(EHH+KTOP)) : (Wls + (o-KTOP)*(EHH+KTOP));
            float s = 0.f;
            for (int j = lane; j < EHH+KTOP; j += 32) s += W[j]*inp[j];
            s = warp_sum(s);
            if (lane == 0) {
                if (o < KTOP) mu_s[o] = s + bmu[o];
                else          ls_s[o-KTOP] = s + bls[o-KTOP];
            }
        }
        __syncthreads();
        if (tid < KTOP) {
            float mu = mu_s[tid], ls = ls_s[tid];
            float term;
            if (t == 0) term = 0.5f*((__expf(ls) + mu*mu)/(1.f+EPSF) - 1.f - ls);
            else {
                float dd = mu - eta_s[tid];
                term = 0.5f*((__expf(ls) + dd*dd)/(DELTAF+EPSF) - 1.f + LOGDF - ls);
            }
            kl_acc += term;
            d_eta[t*KTOP + tid] = mu;
        }
        __syncthreads();
        if (tid < KTOP) eta_s[tid] = mu_s[tid];
        __syncthreads();
    }
    block_add_double(kl_acc, 2);
}

// ------------- theta hidden epilogue -------------
__global__ void k_theta_h(const float* __restrict__ b_theta, const float* __restrict__ W_theta,
                          const int* __restrict__ times) {
    int idx = blockIdx.x * blockDim.x + threadIdx.x;
    if (idx >= BB*THH) return;
    int b = idx / THH, i = idx % THH;
    int tb = times[b];
    float v = d_hth[idx] + b_theta[i];
    const float* wrow = W_theta + (size_t)i*(VV+KTOP) + VV;
    const float* er = d_eta + tb*KTOP;
#pragma unroll 10
    for (int k = 0; k < KTOP; k++) v += er[k]*wrow[k];
    d_hth[idx] = tanhf(v);
}

// ------------- mu_t / ls_t -------------
__global__ void k_theta_muls(const float* __restrict__ Wmu, const float* __restrict__ bmu,
                             const float* __restrict__ Wls, const float* __restrict__ bls) {
    int w = (blockIdx.x * blockDim.x + threadIdx.x) >> 5;
    int lane = threadIdx.x & 31;
    if (w >= BB*2*KTOP) return;
    int b = w / (2*KTOP), q = w % (2*KTOP);
    int kk = q % KTOP;
    bool isls = q >= KTOP;
    const float* W = (isls ? Wls : Wmu) + kk*THH;
    const float* h = d_hth + b*THH;
    float s = 0.f;
    for (int j = lane; j < THH; j += 32) s += W[j]*h[j];
    s = warp_sum(s);
    if (lane == 0) {
        s += (isls ? bls : bmu)[kk];
        (isls ? d_ls_t : d_mu_t)[b*KTOP + kk] = s;
    }
}

// ------------- theta softmax + kl_theta -------------
__global__ void k_theta_softkl(const int* __restrict__ times) {
    __shared__ float mus[KTOP], es[KTOP], red2[2];
    int b = blockIdx.x, tid = threadIdx.x;
    if (tid < KTOP) mus[tid] = d_mu_t[b*KTOP + tid];
    __syncthreads();
    if (tid == 0) {
        float m = -1e30f;
        for (int k = 0; k < KTOP; k++) m = fmaxf(m, mus[k]);
        red2[0] = m;
    }
    __syncthreads();
    if (tid < KTOP) es[tid] = __expf(mus[tid] - red2[0]);
    __syncthreads();
    if (tid == 0) {
        float s = 0.f;
        for (int k = 0; k < KTOP; k++) s += es[k];
        red2[1] = 1.f/s;
    }
    __syncthreads();
    float kl = 0.f;
    if (tid < KTOP) {
        d_theta[b*KTOP + tid] = es[tid]*red2[1];
        float ls = d_ls_t[b*KTOP + tid];
        float e  = d_eta[times[b]*KTOP + tid];
        float dmu = mus[tid] - e;
        kl = 0.5f*((__expf(ls) + dmu*dmu)/(1.f+EPSF) - 1.f - ls);
    }
    block_add_double(kl, 3);
}

// ------------- kl_alpha -------------
__global__ void k_klalpha(const float* __restrict__ mq, const float* __restrict__ lsq) {
    int idx = blockIdx.x * blockDim.x + threadIdx.x;
    float term = 0.f;
    if (idx < KTOP*TT*EE) {
        int t = (idx / EE) % TT;
        float mu = mq[idx], ls = lsq[idx];
        if (t == 0) term = 0.5f*((__expf(ls) + mu*mu)/(1.f+EPSF) - 1.f - ls);
        else {
            float d = mu - mq[idx - EE];
            term = 0.5f*((__expf(ls) + d*d)/(DELTAF+EPSF) - 1.f + LOGDF - ls);
        }
    }
    block_add_double(term, 1);
}

// ------------- nll: grid (B, VP/256), b fastest for L2 reuse -------------
__global__ void k_nll(const float* __restrict__ bows, const int* __restrict__ times) {
    __shared__ float wsh[KTOP];
    int b = blockIdx.x;
    int t = times[b];
    int tid = threadIdx.x;
    if (tid < KTOP) {
        int row = t*KTOP + tid;
        wsh[tid] = d_theta[b*KTOP + tid] / d_rowsum[row];
    }
    __syncthreads();
    int v = blockIdx.y * 256 + tid;
    float val = 0.f;
    if (v < VV) {
        const float* base = d_elog + (size_t)(t*KTOP)*VP + v;
        float p = 0.f;
#pragma unroll 10
        for (int k = 0; k < KTOP; k++)
            p += wsh[k] * base[(size_t)k*VP];
        val = __logf(p + EPSF) * bows[(size_t)b*VV + v];
    }
    block_add_double(val, 0);
}

// ------------- finalize -------------
__global__ void k_finalize(float* out, int n) {
    if (threadIdx.x == 0) {
        float nll = -(float)d_scald[0];
        float ka = (float)d_scald[1];
        float ke = (float)d_scald[2];
        float kt = (float)d_scald[3];
        float vals[5] = {nll + ka + ke + kt, nll, ka, ke, kt};
        for (int i = 0; i < n; i++) out[i] = (i < 5) ? vals[i] : 0.f;
    }
}

extern "C" void kernel_launch(void* const* d_in, const int* in_sizes, int n_in,
                              void* d_out, int out_size) {
    const float* bows      = (const float*)d_in[0];
    const float* nbows     = (const float*)d_in[1];
    const float* rnn_inp   = (const float*)d_in[2];
    const float* word_emb  = (const float*)d_in[3];
    const float* mu_q_a    = (const float*)d_in[4];
    const float* ls_q_a    = (const float*)d_in[5];
    const float* W_theta   = (const float*)d_in[6];
    const float* b_theta   = (const float*)d_in[7];
    const float* W_mu_th   = (const float*)d_in[8];
    const float* b_mu_th   = (const float*)d_in[9];
    const float* W_ls_th   = (const float*)d_in[10];
    const float* b_ls_th   = (const float*)d_in[11];
    const float* W_map     = (const float*)d_in[12];
    const float* b_map     = (const float*)d_in[13];
    const float* lstm_Wih  = (const float*)d_in[14];
    const float* lstm_Whh  = (const float*)d_in[15];
    const float* lstm_bih  = (const float*)d_in[16];
    const float* lstm_bhh  = (const float*)d_in[17];
    const float* W_mu_eta  = (const float*)d_in[18];
    const float* b_mu_eta  = (const float*)d_in[19];
    const float* W_ls_eta  = (const float*)d_in[20];
    const float* b_ls_eta  = (const float*)d_in[21];
    const int*   times     = (const int*)d_in[22];
    float* out = (float*)d_out;

    float *dx, *dy, *dhth, *dalph, *dwemb, *delog, *drsum;
    cudaGetSymbolAddress((void**)&dx, d_x);
    cudaGetSymbolAddress((void**)&dy, d_y);
    cudaGetSymbolAddress((void**)&dhth, d_hth);
    cudaGetSymbolAddress((void**)&dalph, d_alphas);
    cudaGetSymbolAddress((void**)&dwemb, d_wembp);
    cudaGetSymbolAddress((void**)&delog, d_elog);
    cudaGetSymbolAddress((void**)&drsum, d_rowsum);

    k_zero<<<(BB*THH + 255)/256, 256>>>();
    k_pack_whh<<<(LL*4*EHH*EHH + 255)/256, 256>>>(lstm_Whh);
    k_alphaT<<<(MP*EP + 255)/256, 256>>>(mu_q_a);
    k_wembpad<<<(int)(((size_t)VP*EP + 255)/256), 256>>>(word_emb);

    // x = rnn_inp @ W_map^T : M=40, N=200, K=30000, split-K z=25
    {
        dim3 g((EHH + 63)/64, (TT + 63)/64, 25);
        k_sgemm_atomic<<<g, 256>>>(rnn_inp, VV, W_map, VV, dx, TT, EHH, 1200);
    }
    k_addbias<<<(TT*EHH + 255)/256, 256>>>(b_map);

    // LSTM layers (ping-pong x/y)
    float* lin = dx; float* lout = dy;
    for (int l = 0; l < LL; l++) {
        k_gin<<<(TT*4*EHH*32 + 255)/256, 256>>>(lstm_Wih, lstm_bih, lstm_bhh, lin, l);
        k_lstm_rec<<<1, 800>>>(lout, l);
        float* tmp = lin; lin = lout; lout = tmp;
    }
    if (lin != dy)
        cudaMemcpyAsync(dy, lin, TT*EHH*sizeof(float), cudaMemcpyDeviceToDevice);

    k_eta<<<1, 256>>>(W_mu_eta, b_mu_eta, W_ls_eta, b_ls_eta);

    // hth = nbows @ W_theta[:, :V]^T : M=100 N=800 K=30000, split-K z=30 (kchunk=1000)
    {
        dim3 g((THH + 127)/128, 1, 30);
        k_gemm_f32x2<0><<<g, 256>>>(nbows, VV, BB, W_theta, VV + KTOP, THH,
                                    dhth, THH, 1000, nullptr);
    }
    k_theta_h<<<(BB*THH + 255)/256, 256>>>(b_theta, W_theta, times);
    k_theta_muls<<<(BB*2*KTOP*32 + 255)/256, 256>>>(W_mu_th, b_mu_th, W_ls_th, b_ls_th);
    k_theta_softkl<<<BB, 64>>>(times);

    k_klalpha<<<(KTOP*TT*EE + 255)/256, 256>>>(mu_q_a, ls_q_a);

    // logits: single big GEMM with exp+rowsum epilogue, full K = EP
    {
        dim3 g(VP/128, MP/128);
        k_gemm_f32x2<1><<<g, 256>>>(dalph, EP, MP, dwemb, EP, VP,
                                    delog, VP, EP, drsum);
    }

    // nll
    {
        dim3 g(BB, (VV + 255)/256);
        k_nll<<<g, 256>>>(bows, times);
    }

    k_finalize<<<1, 32>>>(out, out_size);
}

// round 7
// speedup vs baseline: 1.7121x; 1.4073x over previous
#include <cuda_runtime.h>
#include <cuda_bf16.h>
#include <math.h>

#define KTOP 50
#define TT   40
#define VV   30000
#define VP   30080          // 235*128
#define THH  800
#define EHH  200
#define EE   300
#define EP   304            // padded E (multiple of 8, = 19*16)
#define LL   3
#define BB   100
#define MP   2048           // padded logits rows (16*128), real rows = 2000

#define EPSF   1e-6f
#define DELTAF 0.005f
#define LOGDF  -5.2983173665480363f

#define SMS32 156           // smem row stride in 32-bit words (= 312 bf16)

// ------------- static device scratch -------------
__device__ float  d_x[TT*EHH];
__device__ float  d_y[TT*EHH];
__device__ float  d_gin[TT*4*EHH];
__device__ float  d_whh4[LL*4*EHH*EHH];
__device__ float  d_eta[TT*KTOP];
__device__ __nv_bfloat16 d_alphab[MP*EP];           // bf16 alphas [MP][EP]
__device__ __nv_bfloat16 d_wembb[(size_t)VP*EP];    // bf16 word_emb [VP][EP]
__device__ float  d_hth[BB*THH];
__device__ float  d_mu_t[BB*KTOP];
__device__ float  d_ls_t[BB*KTOP];
__device__ float  d_theta[BB*KTOP];
__device__ float  d_rowsum[MP];
__device__ double d_scald[4];   // 0:sum(log*bows) 1:kl_alpha 2:kl_eta 3:kl_theta
__device__ __nv_bfloat16 d_elogh[(size_t)MP*VP];    // exp(logits) bf16, ~123 MB

// ------------- helpers -------------
__device__ __forceinline__ float warp_sum(float v) {
#pragma unroll
    for (int o = 16; o; o >>= 1) v += __shfl_xor_sync(0xffffffffu, v, o);
    return v;
}
__device__ __forceinline__ float sigmf(float x) { return 1.f / (1.f + __expf(-x)); }

__device__ __forceinline__ void block_add_double(float v, int slot) {
    __shared__ float red[8];
    int lane = threadIdx.x & 31, wid = threadIdx.x >> 5;
    v = warp_sum(v);
    if (lane == 0) red[wid] = v;
    __syncthreads();
    if (threadIdx.x == 0) {
        float tot = 0.f;
        int nw = (blockDim.x + 31) >> 5;
        for (int w = 0; w < nw; w++) tot += red[w];
        atomicAdd(&d_scald[slot], (double)tot);
    }
}

// ------------- zero -------------
__global__ void k_zero() {
    int i = blockIdx.x * blockDim.x + threadIdx.x;
    if (i < BB*THH) d_hth[i] = 0.f;
    if (i < TT*EHH) d_x[i] = 0.f;
    if (i < MP)     d_rowsum[i] = 0.f;
    if (i < 4)      d_scald[i] = 0.0;
}

// ------------- pack Whh: [l][j4][r][jj] -------------
__global__ void k_pack_whh(const float* __restrict__ Whh) {
    int idx = blockIdx.x * blockDim.x + threadIdx.x;
    if (idx >= LL*4*EHH*EHH) return;
    int l = idx / (4*EHH*EHH);
    int rem = idx % (4*EHH*EHH);
    int j4 = rem / (4*EHH*4);
    int rem2 = rem % (4*EHH*4);
    int r = rem2 >> 2, jj = rem2 & 3;
    d_whh4[idx] = Whh[l*4*EHH*EHH + r*EHH + j4*4 + jj];
}

// ------------- bf16 conversions: alphas transpose+pad, word_emb pad -------------
__global__ void k_alphaT(const float* __restrict__ mq) {
    int idx = blockIdx.x * blockDim.x + threadIdx.x;
    if (idx >= MP*EP) return;
    int row = idx / EP, e = idx % EP;
    int t = row / KTOP, k = row % KTOP;
    float v = (row < TT*KTOP && e < EE) ? mq[(k*TT + t)*EE + e] : 0.f;
    d_alphab[idx] = __float2bfloat16_rn(v);
}
__global__ void k_wembpad(const float* __restrict__ we) {
    size_t idx = (size_t)blockIdx.x * blockDim.x + threadIdx.x;
    if (idx >= (size_t)VP*EP) return;
    int v = (int)(idx / EP), e = (int)(idx % EP);
    float x = (v < VV && e < EE) ? we[(size_t)v*EE + e] : 0.f;
    d_wembb[idx] = __float2bfloat16_rn(x);
}

// ------------- generic split-K SGEMM (W_map path) -------------
__global__ void __launch_bounds__(256) k_sgemm_atomic(
        const float* __restrict__ A, int lda,
        const float* __restrict__ B, int ldb,
        float* __restrict__ C, int M, int N, int kchunk) {
    __shared__ float As[8][64];
    __shared__ float Bs[8][64];
    const int k0b = blockIdx.z * kchunk;
    const int bm = blockIdx.y * 64, bn = blockIdx.x * 64;
    const int tid = threadIdx.x;
    const int lr = tid >> 2, lk = (tid & 3) * 2;
    const int tx = tid & 15, ty = tid >> 4;
    float acc[4][4];
#pragma unroll
    for (int i = 0; i < 4; i++)
#pragma unroll
        for (int j = 0; j < 4; j++) acc[i][j] = 0.f;

    const int kend = k0b + kchunk;
    for (int k0 = k0b; k0 < kend; k0 += 8) {
        float2 av = make_float2(0.f,0.f), bv = make_float2(0.f,0.f);
        int am = bm + lr, bn2 = bn + lr;
        if (am < M) av = *(const float2*)&A[(size_t)am*lda + k0 + lk];
        if (bn2 < N) bv = *(const float2*)&B[(size_t)bn2*ldb + k0 + lk];
        As[lk][lr] = av.x; As[lk+1][lr] = av.y;
        Bs[lk][lr] = bv.x; Bs[lk+1][lr] = bv.y;
        __syncthreads();
#pragma unroll
        for (int kk = 0; kk < 8; kk++) {
            float a[4], b[4];
            *(float4*)a = *(const float4*)&As[kk][ty*4];
            *(float4*)b = *(const float4*)&Bs[kk][tx*4];
#pragma unroll
            for (int i = 0; i < 4; i++)
#pragma unroll
                for (int j = 0; j < 4; j++) acc[i][j] += a[i]*b[j];
        }
        __syncthreads();
    }
#pragma unroll
    for (int i = 0; i < 4; i++) {
        int m = bm + ty*4 + i;
        if (m >= M) continue;
#pragma unroll
        for (int j = 0; j < 4; j++) {
            int n = bn + tx*4 + j;
            if (n < N) atomicAdd(&C[(size_t)m*N + n], acc[i][j]);
        }
    }
}

// ------------- f32x2 SGEMM, 128x128 tile, 8x8 microtile (theta path) -------------
__global__ void __launch_bounds__(256, 1) k_gemm_f32x2(
        const float* __restrict__ A, int lda, int M,
        const float* __restrict__ B, int ldb, int N,
        float* __restrict__ C, int ldc, int kchunk) {
    __shared__ float As[2][8][128];
    __shared__ float Bs[2][8][128];
    const int tid = threadIdx.x;
    const int bm = blockIdx.y * 128, bn = blockIdx.x * 128;
    const int ar  = tid >> 1;
    const int akq = (tid & 1) * 4;
    const int tx = tid & 15, ty = tid >> 4;

    const int kk0   = (int)blockIdx.z * kchunk;
    const int kkend = kk0 + kchunk;

    unsigned long long acc[8][4];
#pragma unroll
    for (int i = 0; i < 8; i++)
#pragma unroll
        for (int j = 0; j < 4; j++) acc[i][j] = 0ull;

    auto ldA = [&](int k) -> float4 {
        if (bm + ar >= M) return make_float4(0.f,0.f,0.f,0.f);
        return *(const float4*)&A[(size_t)(bm + ar)*lda + k + akq];
    };
    auto ldB = [&](int k) -> float4 {
        if (bn + ar >= N) return make_float4(0.f,0.f,0.f,0.f);
        const float* p = &B[(size_t)(bn + ar)*ldb + k + akq];
        float2 u = *(const float2*)p;
        float2 v = *(const float2*)(p + 2);
        return make_float4(u.x, u.y, v.x, v.y);
    };

    float4 ra = ldA(kk0), rb = ldB(kk0);
    As[0][akq+0][ar] = ra.x; As[0][akq+1][ar] = ra.y;
    As[0][akq+2][ar] = ra.z; As[0][akq+3][ar] = ra.w;
    Bs[0][akq+0][ar] = rb.x; Bs[0][akq+1][ar] = rb.y;
    Bs[0][akq+2][ar] = rb.z; Bs[0][akq+3][ar] = rb.w;
    __syncthreads();

    const int nit = (kkend - kk0) >> 3;
    for (int it = 0; it < nit; it++) {
        int buf = it & 1;
        if (it + 1 < nit) {
            ra = ldA(kk0 + (it+1)*8);
            rb = ldB(kk0 + (it+1)*8);
        }
#pragma unroll
        for (int kk = 0; kk < 8; kk++) {
            float a[8];
            *(float4*)&a[0] = *(const float4*)&As[buf][kk][ty*8];
            *(float4*)&a[4] = *(const float4*)&As[buf][kk][ty*8 + 4];
            unsigned long long b2[4];
            const unsigned long long* bp = (const unsigned long long*)&Bs[buf][kk][tx*8];
            b2[0] = bp[0]; b2[1] = bp[1]; b2[2] = bp[2]; b2[3] = bp[3];
            unsigned long long a2[8];
#pragma unroll
            for (int i = 0; i < 8; i++)
                asm("mov.b64 %0, {%1, %1};" : "=l"(a2[i]) : "f"(a[i]));
#pragma unroll
            for (int i = 0; i < 8; i++)
#pragma unroll
                for (int j = 0; j < 4; j++)
                    asm("fma.rn.f32x2 %0, %1, %2, %0;"
                        : "+l"(acc[i][j]) : "l"(a2[i]), "l"(b2[j]));
        }
        if (it + 1 < nit) {
            int nb = buf ^ 1;
            As[nb][akq+0][ar] = ra.x; As[nb][akq+1][ar] = ra.y;
            As[nb][akq+2][ar] = ra.z; As[nb][akq+3][ar] = ra.w;
            Bs[nb][akq+0][ar] = rb.x; Bs[nb][akq+1][ar] = rb.y;
            Bs[nb][akq+2][ar] = rb.z; Bs[nb][akq+3][ar] = rb.w;
        }
        __syncthreads();
    }

#pragma unroll
    for (int i = 0; i < 8; i++) {
        int m = bm + ty*8 + i;
        if (m >= M) continue;
#pragma unroll
        for (int j = 0; j < 4; j++) {
            float2 v = *(float2*)&acc[i][j];
            int n = bn + tx*8 + 2*j;
            if (n   < N) atomicAdd(&C[(size_t)m*ldc + n],   v.x);
            if (n+1 < N) atomicAdd(&C[(size_t)m*ldc + n+1], v.y);
        }
    }
}

// ------------- bf16 HMMA logits GEMM: 128x128 tile, exp->bf16 + rowsum -------------
// A = d_alphab [MP][EP], B = d_wembb [VP][EP]; C[m][n] = sum_k A[m,k]*B[n,k]
// grid (VP/128, MP/128), 256 threads = 8 warps (2 M-strips x 4 N-strips, warp tile 64x32)
__global__ void __launch_bounds__(256, 1) k_gemm_mma() {
    extern __shared__ unsigned int smw[];          // [2][128*SMS32]
    unsigned int* sA = smw;
    unsigned int* sB = smw + 128*SMS32;
    const int tid = threadIdx.x;
    const int bm = blockIdx.y * 128, bn = blockIdx.x * 128;

    // load tiles: 128 rows x 38 uint4 each (row stride gmem EP/8=38, smem 39)
    {
        const uint4* gA = (const uint4*)(d_alphab + (size_t)bm*EP);
        const uint4* gB = (const uint4*)(d_wembb + (size_t)bn*EP);
        uint4* s4A = (uint4*)sA;
        uint4* s4B = (uint4*)sB;
        for (int i = tid; i < 128*38; i += 256) {
            int row = i / 38, c = i % 38;
            s4A[row*39 + c] = gA[row*38 + c];
            s4B[row*39 + c] = gB[row*38 + c];
        }
    }
    __syncthreads();

    const int w   = tid >> 5;
    const int wm  = w & 1;          // 0..1  (M strip of 64)
    const int wn  = w >> 1;         // 0..3  (N strip of 32)
    const int lane = tid & 31;
    const int g = lane >> 2;        // group 0..7
    const int t = lane & 3;         // thread in group

    float c[4][4][4];
#pragma unroll
    for (int mt = 0; mt < 4; mt++)
#pragma unroll
        for (int nt = 0; nt < 4; nt++)
#pragma unroll
            for (int q = 0; q < 4; q++) c[mt][nt][q] = 0.f;

    const unsigned int* sAb = sA + (wm*64 + g)*SMS32 + t;
    const unsigned int* sBb = sB + (wn*32 + g)*SMS32 + t;

    for (int kk = 0; kk < EP/16; kk++) {
        const int ko = kk*8;
        unsigned int a[4][4], b[4][2];
#pragma unroll
        for (int mt = 0; mt < 4; mt++) {
            const unsigned int* p = sAb + mt*16*SMS32 + ko;
            a[mt][0] = p[0];
            a[mt][1] = p[8*SMS32];
            a[mt][2] = p[4];
            a[mt][3] = p[8*SMS32 + 4];
        }
#pragma unroll
        for (int nt = 0; nt < 4; nt++) {
            const unsigned int* p = sBb + nt*8*SMS32 + ko;
            b[nt][0] = p[0];
            b[nt][1] = p[4];
        }
#pragma unroll
        for (int mt = 0; mt < 4; mt++)
#pragma unroll
            for (int nt = 0; nt < 4; nt++)
                asm volatile(
                    "mma.sync.aligned.m16n8k16.row.col.f32.bf16.bf16.f32 "
                    "{%0,%1,%2,%3}, {%4,%5,%6,%7}, {%8,%9}, {%0,%1,%2,%3};"
                    : "+f"(c[mt][nt][0]), "+f"(c[mt][nt][1]),
                      "+f"(c[mt][nt][2]), "+f"(c[mt][nt][3])
                    : "r"(a[mt][0]), "r"(a[mt][1]), "r"(a[mt][2]), "r"(a[mt][3]),
                      "r"(b[nt][0]), "r"(b[nt][1]));
    }

    // epilogue: exp -> bf16 store + fp32 rowsum atomics
#pragma unroll
    for (int mt = 0; mt < 4; mt++) {
        float rs0 = 0.f, rs1 = 0.f;
        int row0 = bm + wm*64 + mt*16 + g;
#pragma unroll
        for (int nt = 0; nt < 4; nt++) {
            int n = bn + wn*32 + nt*8 + t*2;
            float e0 = __expf(c[mt][nt][0]);
            float e1 = __expf(c[mt][nt][1]);
            float e2 = __expf(c[mt][nt][2]);
            float e3 = __expf(c[mt][nt][3]);
            if (n   >= VV) { e0 = 0.f; e2 = 0.f; }
            if (n+1 >= VV) { e1 = 0.f; e3 = 0.f; }
            rs0 += e0 + e1;
            rs1 += e2 + e3;
            *(__nv_bfloat162*)&d_elogh[(size_t)row0*VP + n] =
                __floats2bfloat162_rn(e0, e1);
            *(__nv_bfloat162*)&d_elogh[(size_t)(row0+8)*VP + n] =
                __floats2bfloat162_rn(e2, e3);
        }
        // reduce across the 4 lanes of the group (lane bits 0-1)
        rs0 += __shfl_xor_sync(0xffffffffu, rs0, 1);
        rs0 += __shfl_xor_sync(0xffffffffu, rs0, 2);
        rs1 += __shfl_xor_sync(0xffffffffu, rs1, 1);
        rs1 += __shfl_xor_sync(0xffffffffu, rs1, 2);
        if (t == 0) {
            atomicAdd(&d_rowsum[row0],     rs0);
            atomicAdd(&d_rowsum[row0 + 8], rs1);
        }
    }
}

__global__ void k_addbias(const float* __restrict__ b_map) {
    int i = blockIdx.x * blockDim.x + threadIdx.x;
    if (i < TT*EHH) d_x[i] += b_map[i % EHH];
}

// ------------- LSTM input gates (parallel over t) -------------
__global__ void k_gin(const float* __restrict__ Wih, const float* __restrict__ bih,
                      const float* __restrict__ bhh, const float* __restrict__ x, int l) {
    int w = (blockIdx.x * blockDim.x + threadIdx.x) >> 5;
    int lane = threadIdx.x & 31;
    if (w >= TT*4*EHH) return;
    int t = w / (4*EHH), r = w % (4*EHH);
    const float* wr = Wih + (size_t)l*4*EHH*EHH + (size_t)r*EHH;
    const float* xr = x + t*EHH;
    float s = 0.f;
    for (int j = lane; j < EHH; j += 32) s += wr[j]*xr[j];
    s = warp_sum(s);
    if (lane == 0) d_gin[t*4*EHH + r] = s + bih[l*4*EHH + r] + bhh[l*4*EHH + r];
}

// ------------- LSTM recurrence: single block, 800 threads -------------
__global__ void k_lstm_rec(float* __restrict__ out, int l) {
    __shared__ float h_sh[EHH];
    __shared__ float g_sh[4*EHH];
    int r = threadIdx.x;
    if (r < EHH) h_sh[r] = 0.f;
    float c = 0.f;
    __syncthreads();
    const float4* W = (const float4*)d_whh4 + (size_t)l * (EHH/4) * (4*EHH);
    for (int t = 0; t < TT; t++) {
        float acc = d_gin[t*4*EHH + r];
#pragma unroll 10
        for (int j4 = 0; j4 < EHH/4; j4++) {
            float4 w = W[j4*(4*EHH) + r];
            acc += w.x*h_sh[j4*4] + w.y*h_sh[j4*4+1] + w.z*h_sh[j4*4+2] + w.w*h_sh[j4*4+3];
        }
        g_sh[r] = acc;
        __syncthreads();
        if (r < EHH) {
            float ig = sigmf(g_sh[r]);
            float fg = sigmf(g_sh[EHH + r]);
            float gg = tanhf(g_sh[2*EHH + r]);
            float og = sigmf(g_sh[3*EHH + r]);
            c = fg*c + ig*gg;
            float h = og*tanhf(c);
            h_sh[r] = h;
            out[t*EHH + r] = h;
        }
        __syncthreads();
    }
}

// ------------- eta chain (sequential over T, 1 block) -------------
__global__ void k_eta(const float* __restrict__ Wmu, const float* __restrict__ bmu,
                      const float* __restrict__ Wls, const float* __restrict__ bls) {
    __shared__ float inp[EHH+KTOP];
    __shared__ float mu_s[KTOP], ls_s[KTOP], eta_s[KTOP];
    int tid = threadIdx.x, lane = tid & 31, wid = tid >> 5;
    float kl_acc = 0.f;
    for (int t = 0; t < TT; t++) {
        if (tid < EHH) inp[tid] = d_y[t*EHH + tid];
        else if (tid < EHH+KTOP) inp[tid] = (t == 0) ? 0.f : eta_s[tid - EHH];
        __syncthreads();
        for (int o = wid; o < 2*KTOP; o += 8) {
            const float* W = (o < KTOP) ? (Wmu + o*(EHH+KTOP)) : (Wls + (o-KTOP)*(EHH+KTOP));
            float s = 0.f;
            for (int j = lane; j < EHH+KTOP; j += 32) s += W[j]*inp[j];
            s = warp_sum(s);
            if (lane == 0) {
                if (o < KTOP) mu_s[o] = s + bmu[o];
                else          ls_s[o-KTOP] = s + bls[o-KTOP];
            }
        }
        __syncthreads();
        if (tid < KTOP) {
            float mu = mu_s[tid], ls = ls_s[tid];
            float term;
            if (t == 0) term = 0.5f*((__expf(ls) + mu*mu)/(1.f+EPSF) - 1.f - ls);
            else {
                float dd = mu - eta_s[tid];
                term = 0.5f*((__expf(ls) + dd*dd)/(DELTAF+EPSF) - 1.f + LOGDF - ls);
            }
            kl_acc += term;
            d_eta[t*KTOP + tid] = mu;
        }
        __syncthreads();
        if (tid < KTOP) eta_s[tid] = mu_s[tid];
        __syncthreads();
    }
    block_add_double(kl_acc, 2);
}

// ------------- theta hidden epilogue -------------
__global__ void k_theta_h(const float* __restrict__ b_theta, const float* __restrict__ W_theta,
                          const int* __restrict__ times) {
    int idx = blockIdx.x * blockDim.x + threadIdx.x;
    if (idx >= BB*THH) return;
    int b = idx / THH, i = idx % THH;
    int tb = times[b];
    float v = d_hth[idx] + b_theta[i];
    const float* wrow = W_theta + (size_t)i*(VV+KTOP) + VV;
    const float* er = d_eta + tb*KTOP;
#pragma unroll 10
    for (int k = 0; k < KTOP; k++) v += er[k]*wrow[k];
    d_hth[idx] = tanhf(v);
}

// ------------- mu_t / ls_t -------------
__global__ void k_theta_muls(const float* __restrict__ Wmu, const float* __restrict__ bmu,
                             const float* __restrict__ Wls, const float* __restrict__ bls) {
    int w = (blockIdx.x * blockDim.x + threadIdx.x) >> 5;
    int lane = threadIdx.x & 31;
    if (w >= BB*2*KTOP) return;
    int b = w / (2*KTOP), q = w % (2*KTOP);
    int kk = q % KTOP;
    bool isls = q >= KTOP;
    const float* W = (isls ? Wls : Wmu) + kk*THH;
    const float* h = d_hth + b*THH;
    float s = 0.f;
    for (int j = lane; j < THH; j += 32) s += W[j]*h[j];
    s = warp_sum(s);
    if (lane == 0) {
        s += (isls ? bls : bmu)[kk];
        (isls ? d_ls_t : d_mu_t)[b*KTOP + kk] = s;
    }
}

// ------------- theta softmax + kl_theta -------------
__global__ void k_theta_softkl(const int* __restrict__ times) {
    __shared__ float mus[KTOP], es[KTOP], red2[2];
    int b = blockIdx.x, tid = threadIdx.x;
    if (tid < KTOP) mus[tid] = d_mu_t[b*KTOP + tid];
    __syncthreads();
    if (tid == 0) {
        float m = -1e30f;
        for (int k = 0; k < KTOP; k++) m = fmaxf(m, mus[k]);
        red2[0] = m;
    }
    __syncthreads();
    if (tid < KTOP) es[tid] = __expf(mus[tid] - red2[0]);
    __syncthreads();
    if (tid == 0) {
        float s = 0.f;
        for (int k = 0; k < KTOP; k++) s += es[k];
        red2[1] = 1.f/s;
    }
    __syncthreads();
    float kl = 0.f;
    if (tid < KTOP) {
        d_theta[b*KTOP + tid] = es[tid]*red2[1];
        float ls = d_ls_t[b*KTOP + tid];
        float e  = d_eta[times[b]*KTOP + tid];
        float dmu = mus[tid] - e;
        kl = 0.5f*((__expf(ls) + dmu*dmu)/(1.f+EPSF) - 1.f - ls);
    }
    block_add_double(kl, 3);
}

// ------------- kl_alpha -------------
__global__ void k_klalpha(const float* __restrict__ mq, const float* __restrict__ lsq) {
    int idx = blockIdx.x * blockDim.x + threadIdx.x;
    float term = 0.f;
    if (idx < KTOP*TT*EE) {
        int t = (idx / EE) % TT;
        float mu = mq[idx], ls = lsq[idx];
        if (t == 0) term = 0.5f*((__expf(ls) + mu*mu)/(1.f+EPSF) - 1.f - ls);
        else {
            float d = mu - mq[idx - EE];
            term = 0.5f*((__expf(ls) + d*d)/(DELTAF+EPSF) - 1.f + LOGDF - ls);
        }
    }
    block_add_double(term, 1);
}

// ------------- nll: grid (B, VP/256) -------------
__global__ void k_nll(const float* __restrict__ bows, const int* __restrict__ times) {
    __shared__ float wsh[KTOP];
    int b = blockIdx.x;
    int t = times[b];
    int tid = threadIdx.x;
    if (tid < KTOP) {
        int row = t*KTOP + tid;
        wsh[tid] = d_theta[b*KTOP + tid] / d_rowsum[row];
    }
    __syncthreads();
    int v = blockIdx.y * 256 + tid;
    float val = 0.f;
    if (v < VV) {
        const __nv_bfloat16* base = d_elogh + (size_t)(t*KTOP)*VP + v;
        float p = 0.f;
#pragma unroll 10
        for (int k = 0; k < KTOP; k++)
            p += wsh[k] * __bfloat162float(base[(size_t)k*VP]);
        val = __logf(p + EPSF) * bows[(size_t)b*VV + v];
    }
    block_add_double(val, 0);
}

// ------------- finalize -------------
__global__ void k_finalize(float* out, int n) {
    if (threadIdx.x == 0) {
        float nll = -(float)d_scald[0];
        float ka = (float)d_scald[1];
        float ke = (float)d_scald[2];
        float kt = (float)d_scald[3];
        float vals[5] = {nll + ka + ke + kt, nll, ka, ke, kt};
        for (int i = 0; i < n; i++) out[i] = (i < 5) ? vals[i] : 0.f;
    }
}

extern "C" void kernel_launch(void* const* d_in, const int* in_sizes, int n_in,
                              void* d_out, int out_size) {
    const float* bows      = (const float*)d_in[0];
    const float* nbows     = (const float*)d_in[1];
    const float* rnn_inp   = (const float*)d_in[2];
    const float* word_emb  = (const float*)d_in[3];
    const float* mu_q_a    = (const float*)d_in[4];
    const float* ls_q_a    = (const float*)d_in[5];
    const float* W_theta   = (const float*)d_in[6];
    const float* b_theta   = (const float*)d_in[7];
    const float* W_mu_th   = (const float*)d_in[8];
    const float* b_mu_th   = (const float*)d_in[9];
    const float* W_ls_th   = (const float*)d_in[10];
    const float* b_ls_th   = (const float*)d_in[11];
    const float* W_map     = (const float*)d_in[12];
    const float* b_map     = (const float*)d_in[13];
    const float* lstm_Wih  = (const float*)d_in[14];
    const float* lstm_Whh  = (const float*)d_in[15];
    const float* lstm_bih  = (const float*)d_in[16];
    const float* lstm_bhh  = (const float*)d_in[17];
    const float* W_mu_eta  = (const float*)d_in[18];
    const float* b_mu_eta  = (const float*)d_in[19];
    const float* W_ls_eta  = (const float*)d_in[20];
    const float* b_ls_eta  = (const float*)d_in[21];
    const int*   times     = (const int*)d_in[22];
    float* out = (float*)d_out;

    float *dx, *dy, *dhth;
    cudaGetSymbolAddress((void**)&dx, d_x);
    cudaGetSymbolAddress((void**)&dy, d_y);
    cudaGetSymbolAddress((void**)&dhth, d_hth);

    static int smem_set = 0;
    const int mma_smem = 2 * 128 * SMS32 * 4;   // 159744 bytes
    if (!smem_set) {
        cudaFuncSetAttribute(k_gemm_mma,
            cudaFuncAttributeMaxDynamicSharedMemorySize, mma_smem);
        smem_set = 1;
    }

    k_zero<<<(BB*THH + 255)/256, 256>>>();
    k_pack_whh<<<(LL*4*EHH*EHH + 255)/256, 256>>>(lstm_Whh);
    k_alphaT<<<(MP*EP + 255)/256, 256>>>(mu_q_a);
    k_wembpad<<<(int)(((size_t)VP*EP + 255)/256), 256>>>(word_emb);

    // x = rnn_inp @ W_map^T : M=40, N=200, K=30000, split-K z=25
    {
        dim3 g((EHH + 63)/64, (TT + 63)/64, 25);
        k_sgemm_atomic<<<g, 256>>>(rnn_inp, VV, W_map, VV, dx, TT, EHH, 1200);
    }
    k_addbias<<<(TT*EHH + 255)/256, 256>>>(b_map);

    // LSTM layers (ping-pong x/y)
    float* lin = dx; float* lout = dy;
    for (int l = 0; l < LL; l++) {
        k_gin<<<(TT*4*EHH*32 + 255)/256, 256>>>(lstm_Wih, lstm_bih, lstm_bhh, lin, l);
        k_lstm_rec<<<1, 800>>>(lout, l);
        float* tmp = lin; lin = lout; lout = tmp;
    }
    if (lin != dy)
        cudaMemcpyAsync(dy, lin, TT*EHH*sizeof(float), cudaMemcpyDeviceToDevice);

    k_eta<<<1, 256>>>(W_mu_eta, b_mu_eta, W_ls_eta, b_ls_eta);

    // hth = nbows @ W_theta[:, :V]^T : split-K z=30 (kchunk=1000)
    {
        dim3 g((THH + 127)/128, 1, 30);
        k_gemm_f32x2<<<g, 256>>>(nbows, VV, BB, W_theta, VV + KTOP, THH,
                                 dhth, THH, 1000);
    }
    k_theta_h<<<(BB*THH + 255)/256, 256>>>(b_theta, W_theta, times);
    k_theta_muls<<<(BB*2*KTOP*32 + 255)/256, 256>>>(W_mu_th, b_mu_th, W_ls_th, b_ls_th);
    k_theta_softkl<<<BB, 64>>>(times);

    k_klalpha<<<(KTOP*TT*EE + 255)/256, 256>>>(mu_q_a, ls_q_a);

    // logits: bf16 tensor-core GEMM with exp+rowsum epilogue
    {
        dim3 g(VP/128, MP/128);
        k_gemm_mma<<<g, 256, mma_smem>>>();
    }

    // nll
    {
        dim3 g(BB, (VV + 255)/256);
        k_nll<<<g, 256>>>(bows, times);
    }

    k_finalize<<<1, 32>>>(out, out_size);
}

// round 9
// speedup vs baseline: 2.6344x; 1.5387x over previous
#include <cuda_runtime.h>
#include <cuda_bf16.h>
#include <math.h>

#define KTOP 50
#define TT   40
#define VV   30000
#define VP   30080          // 235*128
#define THH  800
#define EHH  200
#define EE   300
#define EP   304            // padded E (multiple of 8, = 19*16)
#define LL   3
#define BB   100
#define MP   2048           // padded logits rows (16*128), real rows = 2000

#define EPSF   1e-6f
#define DELTAF 0.005f
#define LOGDF  -5.2983173665480363f

#define SMS32 156           // mma smem row stride in 32-bit words (= 312 bf16)

// LSTM persistent kernel config
#define NBLK 8              // blocks; each owns EHH/NBLK = 25 h-elements
#define HSL  (EHH/NBLK)     // 25
#define LROWS (4*HSL)       // 100 gate rows per block
#define LSTR 204            // smem row stride (floats), mult of 4, conflict-free LDS.128

// ------------- static device scratch -------------
__device__ float  d_x[TT*EHH];
__device__ float  d_y[TT*EHH];
__device__ float  d_gin[TT*4*EHH];
__device__ float  d_eta[TT*KTOP];
__device__ __nv_bfloat16 d_alphab[MP*EP];           // bf16 alphas [MP][EP]
__device__ __nv_bfloat16 d_wembb[(size_t)VP*EP];    // bf16 word_emb [VP][EP]
__device__ float  d_hth[BB*THH];
__device__ float  d_mu_t[BB*KTOP];
__device__ float  d_ls_t[BB*KTOP];
__device__ float  d_theta[BB*KTOP];
__device__ float  d_rowsum[MP];
__device__ double d_scald[4];   // 0:sum(log*bows) 1:kl_alpha 2:kl_eta 3:kl_theta
__device__ __nv_bfloat16 d_elogh[(size_t)MP*VP];    // exp(logits) bf16, ~123 MB
__device__ unsigned int d_syncv[LL];                // per-layer arrival counters
__device__ float  d_hbuf2[2][EHH];                  // double-buffered h exchange

// ------------- helpers -------------
__device__ __forceinline__ float warp_sum(float v) {
#pragma unroll
    for (int o = 16; o; o >>= 1) v += __shfl_xor_sync(0xffffffffu, v, o);
    return v;
}
__device__ __forceinline__ float sigmf(float x) { return 1.f / (1.f + __expf(-x)); }

__device__ __forceinline__ void block_add_double(float v, int slot) {
    __shared__ float red[8];
    int lane = threadIdx.x & 31, wid = threadIdx.x >> 5;
    v = warp_sum(v);
    if (lane == 0) red[wid] = v;
    __syncthreads();
    if (threadIdx.x == 0) {
        float tot = 0.f;
        int nw = (blockDim.x + 31) >> 5;
        for (int w = 0; w < nw; w++) tot += red[w];
        atomicAdd(&d_scald[slot], (double)tot);
    }
}

// ------------- zero -------------
__global__ void k_zero() {
    int i = blockIdx.x * blockDim.x + threadIdx.x;
    if (i < BB*THH) d_hth[i] = 0.f;
    if (i < TT*EHH) d_x[i] = 0.f;
    if (i < MP)     d_rowsum[i] = 0.f;
    if (i < 4)      d_scald[i] = 0.0;
    if (i < LL)     d_syncv[i] = 0u;
}

// ------------- bf16 conversions -------------
__global__ void k_alphaT(const float* __restrict__ mq) {
    int idx = blockIdx.x * blockDim.x + threadIdx.x;
    if (idx >= MP*EP) return;
    int row = idx / EP, e = idx % EP;
    int t = row / KTOP, k = row % KTOP;
    float v = (row < TT*KTOP && e < EE) ? mq[(k*TT + t)*EE + e] : 0.f;
    d_alphab[idx] = __float2bfloat16_rn(v);
}
__global__ void k_wembpad(const float* __restrict__ we) {
    size_t idx = (size_t)blockIdx.x * blockDim.x + threadIdx.x;
    if (idx >= (size_t)VP*EP) return;
    int v = (int)(idx / EP), e = (int)(idx % EP);
    float x = (v < VV && e < EE) ? we[(size_t)v*EE + e] : 0.f;
    d_wembb[idx] = __float2bfloat16_rn(x);
}

// ------------- generic split-K SGEMM (W_map path) -------------
__global__ void __launch_bounds__(256) k_sgemm_atomic(
        const float* __restrict__ A, int lda,
        const float* __restrict__ B, int ldb,
        float* __restrict__ C, int M, int N, int kchunk) {
    __shared__ float As[8][64];
    __shared__ float Bs[8][64];
    const int k0b = blockIdx.z * kchunk;
    const int bm = blockIdx.y * 64, bn = blockIdx.x * 64;
    const int tid = threadIdx.x;
    const int lr = tid >> 2, lk = (tid & 3) * 2;
    const int tx = tid & 15, ty = tid >> 4;
    float acc[4][4];
#pragma unroll
    for (int i = 0; i < 4; i++)
#pragma unroll
        for (int j = 0; j < 4; j++) acc[i][j] = 0.f;

    const int kend = k0b + kchunk;
    for (int k0 = k0b; k0 < kend; k0 += 8) {
        float2 av = make_float2(0.f,0.f), bv = make_float2(0.f,0.f);
        int am = bm + lr, bn2 = bn + lr;
        if (am < M) av = *(const float2*)&A[(size_t)am*lda + k0 + lk];
        if (bn2 < N) bv = *(const float2*)&B[(size_t)bn2*ldb + k0 + lk];
        As[lk][lr] = av.x; As[lk+1][lr] = av.y;
        Bs[lk][lr] = bv.x; Bs[lk+1][lr] = bv.y;
        __syncthreads();
#pragma unroll
        for (int kk = 0; kk < 8; kk++) {
            float a[4], b[4];
            *(float4*)a = *(const float4*)&As[kk][ty*4];
            *(float4*)b = *(const float4*)&Bs[kk][tx*4];
#pragma unroll
            for (int i = 0; i < 4; i++)
#pragma unroll
                for (int j = 0; j < 4; j++) acc[i][j] += a[i]*b[j];
        }
        __syncthreads();
    }
#pragma unroll
    for (int i = 0; i < 4; i++) {
        int m = bm + ty*4 + i;
        if (m >= M) continue;
#pragma unroll
        for (int j = 0; j < 4; j++) {
            int n = bn + tx*4 + j;
            if (n < N) atomicAdd(&C[(size_t)m*N + n], acc[i][j]);
        }
    }
}

// ------------- f32x2 SGEMM, 128x128 tile, 8x8 microtile (theta path) -------------
__global__ void __launch_bounds__(256, 1) k_gemm_f32x2(
        const float* __restrict__ A, int lda, int M,
        const float* __restrict__ B, int ldb, int N,
        float* __restrict__ C, int ldc, int kchunk) {
    __shared__ float As[2][8][128];
    __shared__ float Bs[2][8][128];
    const int tid = threadIdx.x;
    const int bm = blockIdx.y * 128, bn = blockIdx.x * 128;
    const int ar  = tid >> 1;
    const int akq = (tid & 1) * 4;
    const int tx = tid & 15, ty = tid >> 4;

    const int kk0   = (int)blockIdx.z * kchunk;
    const int kkend = kk0 + kchunk;

    unsigned long long acc[8][4];
#pragma unroll
    for (int i = 0; i < 8; i++)
#pragma unroll
        for (int j = 0; j < 4; j++) acc[i][j] = 0ull;

    auto ldA = [&](int k) -> float4 {
        if (bm + ar >= M) return make_float4(0.f,0.f,0.f,0.f);
        return *(const float4*)&A[(size_t)(bm + ar)*lda + k + akq];
    };
    auto ldB = [&](int k) -> float4 {
        if (bn + ar >= N) return make_float4(0.f,0.f,0.f,0.f);
        const float* p = &B[(size_t)(bn + ar)*ldb + k + akq];
        float2 u = *(const float2*)p;
        float2 v = *(const float2*)(p + 2);
        return make_float4(u.x, u.y, v.x, v.y);
    };

    float4 ra = ldA(kk0), rb = ldB(kk0);
    As[0][akq+0][ar] = ra.x; As[0][akq+1][ar] = ra.y;
    As[0][akq+2][ar] = ra.z; As[0][akq+3][ar] = ra.w;
    Bs[0][akq+0][ar] = rb.x; Bs[0][akq+1][ar] = rb.y;
    Bs[0][akq+2][ar] = rb.z; Bs[0][akq+3][ar] = rb.w;
    __syncthreads();

    const int nit = (kkend - kk0) >> 3;
    for (int it = 0; it < nit; it++) {
        int buf = it & 1;
        if (it + 1 < nit) {
            ra = ldA(kk0 + (it+1)*8);
            rb = ldB(kk0 + (it+1)*8);
        }
#pragma unroll
        for (int kk = 0; kk < 8; kk++) {
            float a[8];
            *(float4*)&a[0] = *(const float4*)&As[buf][kk][ty*8];
            *(float4*)&a[4] = *(const float4*)&As[buf][kk][ty*8 + 4];
            unsigned long long b2[4];
            const unsigned long long* bp = (const unsigned long long*)&Bs[buf][kk][tx*8];
            b2[0] = bp[0]; b2[1] = bp[1]; b2[2] = bp[2]; b2[3] = bp[3];
            unsigned long long a2[8];
#pragma unroll
            for (int i = 0; i < 8; i++)
                asm("mov.b64 %0, {%1, %1};" : "=l"(a2[i]) : "f"(a[i]));
#pragma unroll
            for (int i = 0; i < 8; i++)
#pragma unroll
                for (int j = 0; j < 4; j++)
                    asm("fma.rn.f32x2 %0, %1, %2, %0;"
                        : "+l"(acc[i][j]) : "l"(a2[i]), "l"(b2[j]));
        }
        if (it + 1 < nit) {
            int nb = buf ^ 1;
            As[nb][akq+0][ar] = ra.x; As[nb][akq+1][ar] = ra.y;
            As[nb][akq+2][ar] = ra.z; As[nb][akq+3][ar] = ra.w;
            Bs[nb][akq+0][ar] = rb.x; Bs[nb][akq+1][ar] = rb.y;
            Bs[nb][akq+2][ar] = rb.z; Bs[nb][akq+3][ar] = rb.w;
        }
        __syncthreads();
    }

#pragma unroll
    for (int i = 0; i < 8; i++) {
        int m = bm + ty*8 + i;
        if (m >= M) continue;
#pragma unroll
        for (int j = 0; j < 4; j++) {
            float2 v = *(float2*)&acc[i][j];
            int n = bn + tx*8 + 2*j;
            if (n   < N) atomicAdd(&C[(size_t)m*ldc + n],   v.x);
            if (n+1 < N) atomicAdd(&C[(size_t)m*ldc + n+1], v.y);
        }
    }
}

// ------------- bf16 HMMA logits GEMM: 128x128 tile, exp->bf16 + rowsum -------------
__global__ void __launch_bounds__(256, 1) k_gemm_mma() {
    extern __shared__ unsigned int smw[];          // [2][128*SMS32]
    unsigned int* sA = smw;
    unsigned int* sB = smw + 128*SMS32;
    const int tid = threadIdx.x;
    const int bm = blockIdx.y * 128, bn = blockIdx.x * 128;

    {
        const uint4* gA = (const uint4*)(d_alphab + (size_t)bm*EP);
        const uint4* gB = (const uint4*)(d_wembb + (size_t)bn*EP);
        uint4* s4A = (uint4*)sA;
        uint4* s4B = (uint4*)sB;
        for (int i = tid; i < 128*38; i += 256) {
            int row = i / 38, c = i % 38;
            s4A[row*39 + c] = gA[row*38 + c];
            s4B[row*39 + c] = gB[row*38 + c];
        }
    }
    __syncthreads();

    const int w   = tid >> 5;
    const int wm  = w & 1;
    const int wn  = w >> 1;
    const int lane = tid & 31;
    const int g = lane >> 2;
    const int t = lane & 3;

    float c[4][4][4];
#pragma unroll
    for (int mt = 0; mt < 4; mt++)
#pragma unroll
        for (int nt = 0; nt < 4; nt++)
#pragma unroll
            for (int q = 0; q < 4; q++) c[mt][nt][q] = 0.f;

    const unsigned int* sAb = sA + (wm*64 + g)*SMS32 + t;
    const unsigned int* sBb = sB + (wn*32 + g)*SMS32 + t;

    for (int kk = 0; kk < EP/16; kk++) {
        const int ko = kk*8;
        unsigned int a[4][4], b[4][2];
#pragma unroll
        for (int mt = 0; mt < 4; mt++) {
            const unsigned int* p = sAb + mt*16*SMS32 + ko;
            a[mt][0] = p[0];
            a[mt][1] = p[8*SMS32];
            a[mt][2] = p[4];
            a[mt][3] = p[8*SMS32 + 4];
        }
#pragma unroll
        for (int nt = 0; nt < 4; nt++) {
            const unsigned int* p = sBb + nt*8*SMS32 + ko;
            b[nt][0] = p[0];
            b[nt][1] = p[4];
        }
#pragma unroll
        for (int mt = 0; mt < 4; mt++)
#pragma unroll
            for (int nt = 0; nt < 4; nt++)
                asm volatile(
                    "mma.sync.aligned.m16n8k16.row.col.f32.bf16.bf16.f32 "
                    "{%0,%1,%2,%3}, {%4,%5,%6,%7}, {%8,%9}, {%0,%1,%2,%3};"
                    : "+f"(c[mt][nt][0]), "+f"(c[mt][nt][1]),
                      "+f"(c[mt][nt][2]), "+f"(c[mt][nt][3])
                    : "r"(a[mt][0]), "r"(a[mt][1]), "r"(a[mt][2]), "r"(a[mt][3]),
                      "r"(b[nt][0]), "r"(b[nt][1]));
    }

#pragma unroll
    for (int mt = 0; mt < 4; mt++) {
        float rs0 = 0.f, rs1 = 0.f;
        int row0 = bm + wm*64 + mt*16 + g;
#pragma unroll
        for (int nt = 0; nt < 4; nt++) {
            int n = bn + wn*32 + nt*8 + t*2;
            float e0 = __expf(c[mt][nt][0]);
            float e1 = __expf(c[mt][nt][1]);
            float e2 = __expf(c[mt][nt][2]);
            float e3 = __expf(c[mt][nt][3]);
            if (n   >= VV) { e0 = 0.f; e2 = 0.f; }
            if (n+1 >= VV) { e1 = 0.f; e3 = 0.f; }
            rs0 += e0 + e1;
            rs1 += e2 + e3;
            *(__nv_bfloat162*)&d_elogh[(size_t)row0*VP + n] =
                __floats2bfloat162_rn(e0, e1);
            *(__nv_bfloat162*)&d_elogh[(size_t)(row0+8)*VP + n] =
                __floats2bfloat162_rn(e2, e3);
        }
        rs0 += __shfl_xor_sync(0xffffffffu, rs0, 1);
        rs0 += __shfl_xor_sync(0xffffffffu, rs0, 2);
        rs1 += __shfl_xor_sync(0xffffffffu, rs1, 1);
        rs1 += __shfl_xor_sync(0xffffffffu, rs1, 2);
        if (t == 0) {
            atomicAdd(&d_rowsum[row0],     rs0);
            atomicAdd(&d_rowsum[row0 + 8], rs1);
        }
    }
}

__global__ void k_addbias(const float* __restrict__ b_map) {
    int i = blockIdx.x * blockDim.x + threadIdx.x;
    if (i < TT*EHH) d_x[i] += b_map[i % EHH];
}

// ------------- LSTM input gates (parallel over t) -------------
__global__ void k_gin(const float* __restrict__ Wih, const float* __restrict__ bih,
                      const float* __restrict__ bhh, const float* __restrict__ x, int l) {
    int w = (blockIdx.x * blockDim.x + threadIdx.x) >> 5;
    int lane = threadIdx.x & 31;
    if (w >= TT*4*EHH) return;
    int t = w / (4*EHH), r = w % (4*EHH);
    const float* wr = Wih + (size_t)l*4*EHH*EHH + (size_t)r*EHH;
    const float* xr = x + t*EHH;
    float s = 0.f;
    for (int j = lane; j < EHH; j += 32) s += wr[j]*xr[j];
    s = warp_sum(s);
    if (lane == 0) d_gin[t*4*EHH + r] = s + bih[l*4*EHH + r] + bhh[l*4*EHH + r];
}

// ------------- LSTM recurrence: NBLK persistent blocks, smem-resident Whh -------------
// Block b owns h elements [b*25, (b+1)*25) = 100 gate rows {q*200+b*25+j}.
// One global counter sync per step; h double-buffered in d_hbuf2.
__global__ void __launch_bounds__(256, 1) k_lstm8(
        const float* __restrict__ Whh, float* __restrict__ yout, int l) {
    extern __shared__ float dynsm[];
    float* Wsm  = dynsm;                    // [LROWS][LSTR]
    float* h_sm = Wsm + LROWS*LSTR;         // [EHH]
    float* gacc = h_sm + EHH;               // [2][LROWS]
    float* gsum = gacc + 2*LROWS;           // [LROWS]
    const int tid = threadIdx.x, b = blockIdx.x;

    // load Whh slice: gate row q*200 + b*25 + j  -> smem row q*25+j
    for (int idx = tid; idx < LROWS*EHH; idx += 256) {
        int row = idx / EHH, col = idx % EHH;
        int q = row / HSL, j = row % HSL;
        int grow = q*EHH + b*HSL + j;
        Wsm[row*LSTR + col] = Whh[(size_t)l*4*EHH*EHH + (size_t)grow*EHH + col];
    }
    float c = 0.f;
    if (tid < HSL) d_hbuf2[0][b*HSL + tid] = 0.f;
    __threadfence();
    __syncthreads();
    if (tid == 0) atomicAdd(&d_syncv[l], 1u);
    if (tid == 0) {
        volatile unsigned int* p = &d_syncv[l];
        while (*p < NBLK) { }
    }
    __syncthreads();

    const int myrow = tid % LROWS;          // for tid < 200
    const int myhalf = tid / LROWS;

    for (int t = 0; t < TT; t++) {
        // read h (previous step) from buffer t&1
        if (tid < EHH) h_sm[tid] = ((volatile float*)d_hbuf2[t & 1])[tid];
        __syncthreads();
        if (tid < 2*LROWS) {
            const float4* w4 = (const float4*)(Wsm + myrow*LSTR + myhalf*100);
            const float4* h4 = (const float4*)(h_sm + myhalf*100);
            float acc = 0.f;
#pragma unroll
            for (int jj = 0; jj < 25; jj++) {
                float4 wv = w4[jj], hv = h4[jj];
                acc += wv.x*hv.x + wv.y*hv.y + wv.z*hv.z + wv.w*hv.w;
            }
            gacc[myhalf*LROWS + myrow] = acc;
        }
        __syncthreads();
        if (tid < LROWS) {
            int q = tid / HSL, j = tid % HSL;
            gsum[tid] = gacc[tid] + gacc[LROWS + tid]
                      + d_gin[t*4*EHH + q*EHH + b*HSL + j];
        }
        __syncthreads();
        if (tid < HSL) {
            float ig = sigmf(gsum[tid]);
            float fg = sigmf(gsum[HSL + tid]);
            float gg = tanhf(gsum[2*HSL + tid]);
            float og = sigmf(gsum[3*HSL + tid]);
            c = fg*c + ig*gg;
            float h = og*tanhf(c);
            d_hbuf2[(t + 1) & 1][b*HSL + tid] = h;
            yout[t*EHH + b*HSL + tid] = h;
        }
        __threadfence();
        __syncthreads();
        if (tid == 0) atomicAdd(&d_syncv[l], 1u);
        if (t < TT - 1) {
            if (tid == 0) {
                volatile unsigned int* p = &d_syncv[l];
                unsigned int target = (unsigned int)NBLK * (t + 2);
                while (*p < target) { }
            }
            __syncthreads();
        }
    }
}

// ------------- eta chain (sequential over T, 1 block) -------------
__global__ void k_eta(const float* __restrict__ Wmu, const float* __restrict__ bmu,
                      const float* __restrict__ Wls, const float* __restrict__ bls) {
    __shared__ float inp[EHH+KTOP];
    __shared__ float mu_s[KTOP], ls_s[KTOP], eta_s[KTOP];
    int tid = threadIdx.x, lane = tid & 31, wid = tid >> 5;
    float kl_acc = 0.f;
    for (int t = 0; t < TT; t++) {
        if (tid < EHH) inp[tid] = d_y[t*EHH + tid];
        else if (tid < EHH+KTOP) inp[tid] = (t == 0) ? 0.f : eta_s[tid - EHH];
        __syncthreads();
        for (int o = wid; o < 2*KTOP; o += 8) {
            const float* W = (o < KTOP) ? (Wmu + o*(EHH+KTOP)) : (Wls + (o-KTOP)*(EHH+KTOP));
            float s = 0.f;
            for (int j = lane; j < EHH+KTOP; j += 32) s += W[j]*inp[j];
            s = warp_sum(s);
            if (lane == 0) {
                if (o < KTOP) mu_s[o] = s + bmu[o];
                else          ls_s[o-KTOP] = s + bls[o-KTOP];
            }
        }
        __syncthreads();
        if (tid < KTOP) {
            float mu = mu_s[tid], ls = ls_s[tid];
            float term;
            if (t == 0) term = 0.5f*((__expf(ls) + mu*mu)/(1.f+EPSF) - 1.f - ls);
            else {
                float dd = mu - eta_s[tid];
                term = 0.5f*((__expf(ls) + dd*dd)/(DELTAF+EPSF) - 1.f + LOGDF - ls);
            }
            kl_acc += term;
            d_eta[t*KTOP + tid] = mu;
        }
        __syncthreads();
        if (tid < KTOP) eta_s[tid] = mu_s[tid];
        __syncthreads();
    }
    block_add_double(kl_acc, 2);
}

// ------------- theta hidden epilogue -------------
__global__ void k_theta_h(const float* __restrict__ b_theta, const float* __restrict__ W_theta,
                          const int* __restrict__ times) {
    int idx = blockIdx.x * blockDim.x + threadIdx.x;
    if (idx >= BB*THH) return;
    int b = idx / THH, i = idx % THH;
    int tb = times[b];
    float v = d_hth[idx] + b_theta[i];
    const float* wrow = W_theta + (size_t)i*(VV+KTOP) + VV;
    const float* er = d_eta + tb*KTOP;
#pragma unroll 10
    for (int k = 0; k < KTOP; k++) v += er[k]*wrow[k];
    d_hth[idx] = tanhf(v);
}

// ------------- mu_t / ls_t -------------
__global__ void k_theta_muls(const float* __restrict__ Wmu, const float* __restrict__ bmu,
                             const float* __restrict__ Wls, const float* __restrict__ bls) {
    int w = (blockIdx.x * blockDim.x + threadIdx.x) >> 5;
    int lane = threadIdx.x & 31;
    if (w >= BB*2*KTOP) return;
    int b = w / (2*KTOP), q = w % (2*KTOP);
    int kk = q % KTOP;
    bool isls = q >= KTOP;
    const float* W = (isls ? Wls : Wmu) + kk*THH;
    const float* h = d_hth + b*THH;
    float s = 0.f;
    for (int j = lane; j < THH; j += 32) s += W[j]*h[j];
    s = warp_sum(s);
    if (lane == 0) {
        s += (isls ? bls : bmu)[kk];
        (isls ? d_ls_t : d_mu_t)[b*KTOP + kk] = s;
    }
}

// ------------- theta softmax + kl_theta -------------
__global__ void k_theta_softkl(const int* __restrict__ times) {
    __shared__ float mus[KTOP], es[KTOP], red2[2];
    int b = blockIdx.x, tid = threadIdx.x;
    if (tid < KTOP) mus[tid] = d_mu_t[b*KTOP + tid];
    __syncthreads();
    if (tid == 0) {
        float m = -1e30f;
        for (int k = 0; k < KTOP; k++) m = fmaxf(m, mus[k]);
        red2[0] = m;
    }
    __syncthreads();
    if (tid < KTOP) es[tid] = __expf(mus[tid] - red2[0]);
    __syncthreads();
    if (tid == 0) {
        float s = 0.f;
        for (int k = 0; k < KTOP; k++) s += es[k];
        red2[1] = 1.f/s;
    }
    __syncthreads();
    float kl = 0.f;
    if (tid < KTOP) {
        d_theta[b*KTOP + tid] = es[tid]*red2[1];
        float ls = d_ls_t[b*KTOP + tid];
        float e  = d_eta[times[b]*KTOP + tid];
        float dmu = mus[tid] - e;
        kl = 0.5f*((__expf(ls) + dmu*dmu)/(1.f+EPSF) - 1.f - ls);
    }
    block_add_double(kl, 3);
}

// ------------- kl_alpha -------------
__global__ void k_klalpha(const float* __restrict__ mq, const float* __restrict__ lsq) {
    int idx = blockIdx.x * blockDim.x + threadIdx.x;
    float term = 0.f;
    if (idx < KTOP*TT*EE) {
        int t = (idx / EE) % TT;
        float mu = mq[idx], ls = lsq[idx];
        if (t == 0) term = 0.5f*((__expf(ls) + mu*mu)/(1.f+EPSF) - 1.f - ls);
        else {
            float d = mu - mq[idx - EE];
            term = 0.5f*((__expf(ls) + d*d)/(DELTAF+EPSF) - 1.f + LOGDF - ls);
        }
    }
    block_add_double(term, 1);
}

// ------------- nll -------------
__global__ void k_nll(const float* __restrict__ bows, const int* __restrict__ times) {
    __shared__ float wsh[KTOP];
    int b = blockIdx.x;
    int t = times[b];
    int tid = threadIdx.x;
    if (tid < KTOP) {
        int row = t*KTOP + tid;
        wsh[tid] = d_theta[b*KTOP + tid] / d_rowsum[row];
    }
    __syncthreads();
    int v = blockIdx.y * 256 + tid;
    float val = 0.f;
    if (v < VV) {
        const __nv_bfloat16* base = d_elogh + (size_t)(t*KTOP)*VP + v;
        float p = 0.f;
#pragma unroll 10
        for (int k = 0; k < KTOP; k++)
            p += wsh[k] * __bfloat162float(base[(size_t)k*VP]);
        val = __logf(p + EPSF) * bows[(size_t)b*VV + v];
    }
    block_add_double(val, 0);
}

// ------------- finalize -------------
__global__ void k_finalize(float* out, int n) {
    if (threadIdx.x == 0) {
        float nll = -(float)d_scald[0];
        float ka = (float)d_scald[1];
        float ke = (float)d_scald[2];
        float kt = (float)d_scald[3];
        float vals[5] = {nll + ka + ke + kt, nll, ka, ke, kt};
        for (int i = 0; i < n; i++) out[i] = (i < 5) ? vals[i] : 0.f;
    }
}

extern "C" void kernel_launch(void* const* d_in, const int* in_sizes, int n_in,
                              void* d_out, int out_size) {
    const float* bows      = (const float*)d_in[0];
    const float* nbows     = (const float*)d_in[1];
    const float* rnn_inp   = (const float*)d_in[2];
    const float* word_emb  = (const float*)d_in[3];
    const float* mu_q_a    = (const float*)d_in[4];
    const float* ls_q_a    = (const float*)d_in[5];
    const float* W_theta   = (const float*)d_in[6];
    const float* b_theta   = (const float*)d_in[7];
    const float* W_mu_th   = (const float*)d_in[8];
    const float* b_mu_th   = (const float*)d_in[9];
    const float* W_ls_th   = (const float*)d_in[10];
    const float* b_ls_th   = (const float*)d_in[11];
    const float* W_map     = (const float*)d_in[12];
    const float* b_map     = (const float*)d_in[13];
    const float* lstm_Wih  = (const float*)d_in[14];
    const float* lstm_Whh  = (const float*)d_in[15];
    const float* lstm_bih  = (const float*)d_in[16];
    const float* lstm_bhh  = (const float*)d_in[17];
    const float* W_mu_eta  = (const float*)d_in[18];
    const float* b_mu_eta  = (const float*)d_in[19];
    const float* W_ls_eta  = (const float*)d_in[20];
    const float* b_ls_eta  = (const float*)d_in[21];
    const int*   times     = (const int*)d_in[22];
    float* out = (float*)d_out;

    float *dx, *dy, *dhth;
    cudaGetSymbolAddress((void**)&dx, d_x);
    cudaGetSymbolAddress((void**)&dy, d_y);
    cudaGetSymbolAddress((void**)&dhth, d_hth);

    const int mma_smem  = 2 * 128 * SMS32 * 4;                      // 159744 B
    const int lstm_smem = (LROWS*LSTR + EHH + 2*LROWS + LROWS) * 4; // ~83.6 KB

    static cudaStream_t s2 = nullptr;
    static cudaEvent_t evA = nullptr, evB = nullptr;
    if (s2 == nullptr) {
        cudaFuncSetAttribute(k_gemm_mma,
            cudaFuncAttributeMaxDynamicSharedMemorySize, mma_smem);
        cudaFuncSetAttribute(k_lstm8,
            cudaFuncAttributeMaxDynamicSharedMemorySize, lstm_smem);
        cudaStreamCreateWithFlags(&s2, cudaStreamNonBlocking);
        cudaEventCreateWithFlags(&evA, cudaEventDisableTiming);
        cudaEventCreateWithFlags(&evB, cudaEventDisableTiming);
    }

    // -------- stream 0: zero, then fork --------
    k_zero<<<(BB*THH + 255)/256, 256>>>();
    cudaEventRecord(evA, 0);
    cudaStreamWaitEvent(s2, evA, 0);

    // -------- side stream: chip-wide independent work --------
    k_alphaT<<<(MP*EP + 255)/256, 256, 0, s2>>>(mu_q_a);
    k_wembpad<<<(int)(((size_t)VP*EP + 255)/256), 256, 0, s2>>>(word_emb);
    {   // hth = nbows @ W_theta[:, :V]^T : split-K z=30 (kchunk=1000)
        dim3 g((THH + 127)/128, 1, 30);
        k_gemm_f32x2<<<g, 256, 0, s2>>>(nbows, VV, BB, W_theta, VV + KTOP, THH,
                                        dhth, THH, 1000);
    }
    k_klalpha<<<(KTOP*TT*EE + 255)/256, 256, 0, s2>>>(mu_q_a, ls_q_a);
    {   // logits: bf16 tensor-core GEMM with exp+rowsum epilogue
        dim3 g(VP/128, MP/128);
        k_gemm_mma<<<g, 256, mma_smem, s2>>>();
    }
    cudaEventRecord(evB, s2);

    // -------- stream 0: serial LSTM/eta chain (overlapped with s2) --------
    {   // x = rnn_inp @ W_map^T : M=40, N=200, K=30000, split-K z=25
        dim3 g((EHH + 63)/64, (TT + 63)/64, 25);
        k_sgemm_atomic<<<g, 256>>>(rnn_inp, VV, W_map, VV, dx, TT, EHH, 1200);
    }
    k_addbias<<<(TT*EHH + 255)/256, 256>>>(b_map);

    float* lin = dx; float* lout = dy;
    for (int l = 0; l < LL; l++) {
        k_gin<<<(TT*4*EHH*32 + 255)/256, 256>>>(lstm_Wih, lstm_bih, lstm_bhh, lin, l);
        k_lstm8<<<NBLK, 256, lstm_smem>>>(lstm_Whh, lout, l);
        float* tmp = lin; lin = lout; lout = tmp;
    }
    // after 3 layers (odd count) final output is in d_y

    k_eta<<<1, 256>>>(W_mu_eta, b_mu_eta, W_ls_eta, b_ls_eta);

    // -------- join --------
    cudaStreamWaitEvent(0, evB, 0);

    k_theta_h<<<(BB*THH + 255)/256, 256>>>(b_theta, W_theta, times);
    k_theta_muls<<<(BB*2*KTOP*32 + 255)/256, 256>>>(W_mu_th, b_mu_th, W_ls_th, b_ls_th);
    k_theta_softkl<<<BB, 64>>>(times);

    {
        dim3 g(BB, (VV + 255)/256);
        k_nll<<<g, 256>>>(bows, times);
    }

    k_finalize<<<1, 32>>>(out, out_size);
}